// round 6
// baseline (speedup 1.0000x reference)
#include <cuda_runtime.h>
#include <cuda_bf16.h>
#include <math.h>
#include <stdint.h>

// ---------------------------------------------------------------------------
// TreeLSTM on GB300, mma.sync bf16x3 (tcgen05 feature-gated off on this
// harness's compute_103 target).
// R6: 3-stage single-sync cp.async pipeline in both GEMMs; x pre-split to
// bf16 hi/lo so the leaf GEMM is the same pure-cp.async path as levels.
// D = Ah*Bh + Ah*Bl + Al*Bh, fp32 accumulators, ldmatrix fragment loads.
// ---------------------------------------------------------------------------

#define Hc      128
#define MAXBL   32768
#define NGATE   640
#define KB_LEAF 320

__device__ __align__(128) __nv_bfloat16 g_xhi[MAXBL * KB_LEAF];
__device__ __align__(128) __nv_bfloat16 g_xlo[MAXBL * KB_LEAF];
__device__ __align__(128) __nv_bfloat16 g_hhiA[MAXBL * Hc];
__device__ __align__(128) __nv_bfloat16 g_hloA[MAXBL * Hc];
__device__ __align__(128) __nv_bfloat16 g_hhiB[(MAXBL / 2) * Hc];
__device__ __align__(128) __nv_bfloat16 g_hloB[(MAXBL / 2) * Hc];
__device__ float g_cA[MAXBL * Hc];
__device__ float g_cB[(MAXBL / 2) * Hc];
__device__ float g_gates[(MAXBL / 2) * NGATE];
__device__ __align__(128) __nv_bfloat16 g_Wt_hi[NGATE * 256];     // [640,256] K-major
__device__ __align__(128) __nv_bfloat16 g_Wt_lo[NGATE * 256];
__device__ float g_Wstf[256 * NGATE];                             // [256,640] fp32
__device__ __align__(128) __nv_bfloat16 g_WlfT_hi[256 * KB_LEAF]; // [256,320]
__device__ __align__(128) __nv_bfloat16 g_WlfT_lo[256 * KB_LEAF];

// ------------------------------- helpers -----------------------------------
__device__ __forceinline__ uint32_t smem_u32(const void* p) {
    uint32_t a;
    asm("{ .reg .u64 t; cvta.to.shared.u64 t, %1; cvt.u32.u64 %0, t; }"
        : "=r"(a) : "l"(p));
    return a;
}
#define CP_ASYNC16(dst, src) \
    asm volatile("cp.async.cg.shared.global [%0], [%1], 16;" \
                 :: "r"(dst), "l"(src) : "memory")
#define CP_COMMIT() asm volatile("cp.async.commit_group;" ::: "memory")
#define CP_WAIT1()  asm volatile("cp.async.wait_group 1;"  ::: "memory")
#define CP_WAIT0()  asm volatile("cp.async.wait_group 0;"  ::: "memory")

#define MMA16816(c, a, b)                                                      \
    asm volatile("mma.sync.aligned.m16n8k16.row.col.f32.bf16.bf16.f32 "       \
        "{%0,%1,%2,%3},{%4,%5,%6,%7},{%8,%9},{%0,%1,%2,%3};"                  \
        : "+f"((c)[0]), "+f"((c)[1]), "+f"((c)[2]), "+f"((c)[3])              \
        : "r"((a)[0]), "r"((a)[1]), "r"((a)[2]), "r"((a)[3]),                 \
          "r"((b)[0]), "r"((b)[1]))

__device__ __forceinline__ void ldsm4(uint32_t a, uint32_t& r0, uint32_t& r1,
                                      uint32_t& r2, uint32_t& r3) {
    asm volatile("ldmatrix.sync.aligned.m8n8.x4.shared.b16 {%0,%1,%2,%3}, [%4];"
                 : "=r"(r0), "=r"(r1), "=r"(r2), "=r"(r3) : "r"(a));
}

__device__ __forceinline__ void split_bf16(float w, __nv_bfloat16* hi, __nv_bfloat16* lo) {
    __nv_bfloat16 h = __float2bfloat16(w);
    *hi = h;
    *lo = __float2bfloat16(w - __bfloat162float(h));
}
__device__ __forceinline__ uint32_t pack_bf(__nv_bfloat16 a, __nv_bfloat16 b) {
    __nv_bfloat162 t{a, b};
    return *(uint32_t*)&t;
}
__device__ __forceinline__ float sigf(float x) { return 1.0f / (1.0f + expf(-x)); }

// Stage layout: A_hi | A_lo | B_hi | B_lo, each 128 rows x 128 bytes, xor-swizzled.
#define TILE_B   16384
#define STAGE    65536
#define SMEM_REQ (3 * STAGE + 128)

// One 64-K chunk: 4 k-steps, 48 MMAs each, ldmatrix loads.
__device__ __forceinline__ void stage_compute(uint32_t st, int wm, int wn, int lane,
                                              float (*acc)[4][4])
{
    const int ts = lane >> 3, rs = lane & 7;
    const uint32_t Ah = st, Al = st + TILE_B, Bh = st + 2 * TILE_B, Bl = st + 3 * TILE_B;
    const int arow = wm * 64 + ((ts & 1) << 3) + rs;
    const int ach  = ts >> 1;
    const int brow = wn * 32 + ((ts >> 1) << 3) + rs;
    const int bch  = ts & 1;
    #pragma unroll
    for (int kk = 0; kk < 4; kk++) {
        uint32_t ah[4][4], al[4][4], bh[4][2], bl[4][2];
        #pragma unroll
        for (int am = 0; am < 4; am++) {
            uint32_t off = (uint32_t)((arow + am * 16) * 128)
                         + (((uint32_t)((kk * 2 + ach) ^ rs)) << 4);
            ldsm4(Ah + off, ah[am][0], ah[am][1], ah[am][2], ah[am][3]);
            ldsm4(Al + off, al[am][0], al[am][1], al[am][2], al[am][3]);
        }
        #pragma unroll
        for (int j = 0; j < 2; j++) {
            uint32_t off = (uint32_t)((brow + j * 16) * 128)
                         + (((uint32_t)((kk * 2 + bch) ^ rs)) << 4);
            ldsm4(Bh + off, bh[2*j][0], bh[2*j][1], bh[2*j+1][0], bh[2*j+1][1]);
            ldsm4(Bl + off, bl[2*j][0], bl[2*j][1], bl[2*j+1][0], bl[2*j+1][1]);
        }
        #pragma unroll
        for (int am = 0; am < 4; am++)
            #pragma unroll
            for (int an = 0; an < 4; an++) {
                MMA16816(acc[am][an], ah[am], bh[an]);
                MMA16816(acc[am][an], ah[am], bl[an]);
                MMA16816(acc[am][an], al[am], bh[an]);
            }
    }
}

// Issue one 64-K chunk of A/B hi+lo tiles into stage (ch%3).
__device__ __forceinline__ void issue_chunk(uint32_t sbase, int ch, int tid,
                                            const __nv_bfloat16* Ahi, const __nv_bfloat16* Alo,
                                            int arow0, int aKB,
                                            const __nv_bfloat16* Bhi, const __nv_bfloat16* Blo,
                                            int brow0, int bKB)
{
    uint32_t st = sbase + (uint32_t)(ch % 3) * STAGE;
    #pragma unroll
    for (int i = 0; i < 8; i++) {            // A hi/lo
        int e = tid + i * 256;
        int mat = e >> 10;
        int rem = e & 1023;
        int row = rem >> 3, chunk = rem & 7;
        const __nv_bfloat16* src = (mat ? Alo : Ahi)
            + (size_t)(arow0 + row) * aKB + ch * 64 + chunk * 8;
        uint32_t dst = st + mat * TILE_B + row * 128 + ((chunk ^ (row & 7)) << 4);
        CP_ASYNC16(dst, src);
    }
    #pragma unroll
    for (int i = 0; i < 8; i++) {            // B hi/lo
        int e = tid + i * 256;
        int mat = e >> 10;
        int rem = e & 1023;
        int row = rem >> 3, chunk = rem & 7;
        const __nv_bfloat16* src = (mat ? Blo : Bhi)
            + (size_t)(brow0 + row) * bKB + ch * 64 + chunk * 8;
        uint32_t dst = st + 2 * TILE_B + mat * TILE_B + row * 128
                     + ((chunk ^ (row & 7)) << 4);
        CP_ASYNC16(dst, src);
    }
}

// ------------------------ weight / input prep ------------------------------
__global__ void prep_wst(const float* __restrict__ Wl, const float* __restrict__ Wr,
                         __nv_bfloat16* __restrict__ hi, __nv_bfloat16* __restrict__ lo,
                         float* __restrict__ Wf)
{
    int idx = blockIdx.x * blockDim.x + threadIdx.x;
    if (idx >= NGATE * 256) return;
    int n = idx >> 8, k = idx & 255;
    float w = (k < 128) ? Wl[k * NGATE + n] : Wr[(k - 128) * NGATE + n];
    split_bf16(w, &hi[idx], &lo[idx]);
    Wf[k * NGATE + n] = w;
}

__global__ void prep_wleaf(const float* __restrict__ W,
                           __nv_bfloat16* __restrict__ hi, __nv_bfloat16* __restrict__ lo)
{
    int idx = blockIdx.x * blockDim.x + threadIdx.x;
    if (idx >= 256 * KB_LEAF) return;
    int n = idx / KB_LEAF, k = idx % KB_LEAF;
    float w = (k < 300) ? W[k * 256 + n] : 0.0f;
    split_bf16(w, &hi[idx], &lo[idx]);
}

// x [BL,300] fp32 -> xhi/xlo [BL,320] bf16 (pad zero). 4 cols/thread.
__global__ void split_x(const float* __restrict__ x,
                        __nv_bfloat16* __restrict__ xhi, __nv_bfloat16* __restrict__ xlo,
                        int BL, int D)
{
    int idx = blockIdx.x * blockDim.x + threadIdx.x;
    if (idx >= BL * 80) return;
    int row = idx / 80, k4 = (idx % 80) * 4;
    uint2 hv = make_uint2(0u, 0u), lv = hv;
    if (k4 < D) {
        float4 v = *(const float4*)(x + (size_t)row * D + k4);
        __nv_bfloat16 h0, l0, h1, l1, h2, l2, h3, l3;
        split_bf16(v.x, &h0, &l0); split_bf16(v.y, &h1, &l1);
        split_bf16(v.z, &h2, &l2); split_bf16(v.w, &h3, &l3);
        hv = make_uint2(pack_bf(h0, h1), pack_bf(h2, h3));
        lv = make_uint2(pack_bf(l0, l1), pack_bf(l2, l3));
    }
    *(uint2*)(xhi + (size_t)row * KB_LEAF + k4) = hv;
    *(uint2*)(xlo + (size_t)row * KB_LEAF + k4) = lv;
}

// ------------------------------ leaf GEMM -----------------------------------
// hc = x @ W_leaf + b_leaf.  ny==0 -> h (hi/lo bf16); ny==1 -> c (f32).
__global__ void __launch_bounds__(256, 1)
gemm_leaf(const __nv_bfloat16* __restrict__ Ahi, const __nv_bfloat16* __restrict__ Alo,
          const __nv_bfloat16* __restrict__ Bhi, const __nv_bfloat16* __restrict__ Blo,
          const float* __restrict__ bias,
          __nv_bfloat16* __restrict__ hhi, __nv_bfloat16* __restrict__ hlo,
          float* __restrict__ cOut, int M)
{
    extern __shared__ char smem[];
    const uint32_t sbase = (smem_u32(smem) + 127) & ~127u;

    const int tid = threadIdx.x;
    const int wid = tid >> 5, lane = tid & 31;
    const int wm = wid >> 2, wn = wid & 3;
    const int g = lane >> 2, t2 = (lane & 3) << 1;
    const int bm = blockIdx.x * 128;
    const int ny = blockIdx.y;
    const int Kc = KB_LEAF / 64;         // 5

    float acc[4][4][4];
    #pragma unroll
    for (int i = 0; i < 4; i++)
        #pragma unroll
        for (int j = 0; j < 4; j++)
            #pragma unroll
            for (int q = 0; q < 4; q++) acc[i][j][q] = 0.f;

    issue_chunk(sbase, 0, tid, Ahi, Alo, bm, KB_LEAF, Bhi, Blo, ny * 128, KB_LEAF);
    CP_COMMIT();
    issue_chunk(sbase, 1, tid, Ahi, Alo, bm, KB_LEAF, Bhi, Blo, ny * 128, KB_LEAF);
    CP_COMMIT();
    for (int ch = 0; ch < Kc; ch++) {
        if (ch + 1 < Kc) CP_WAIT1(); else CP_WAIT0();
        __syncthreads();                               // single barrier per chunk
        if (ch + 2 < Kc) {
            issue_chunk(sbase, ch + 2, tid, Ahi, Alo, bm, KB_LEAF,
                        Bhi, Blo, ny * 128, KB_LEAF);
            CP_COMMIT();
        }
        stage_compute(sbase + (uint32_t)(ch % 3) * STAGE, wm, wn, lane, acc);
    }

    #pragma unroll
    for (int am = 0; am < 4; am++) {
        int r0 = bm + wm * 64 + am * 16 + g;
        #pragma unroll
        for (int an = 0; an < 4; an++) {
            int c  = wn * 32 + an * 8 + t2;
            float b0 = bias[ny * 128 + c], b1 = bias[ny * 128 + c + 1];
            float v00 = acc[am][an][0] + b0, v01 = acc[am][an][1] + b1;
            float v10 = acc[am][an][2] + b0, v11 = acc[am][an][3] + b1;
            if (ny == 0) {
                __nv_bfloat16 h0, l0, h1, l1;
                split_bf16(v00, &h0, &l0); split_bf16(v01, &h1, &l1);
                *(uint32_t*)(hhi + (size_t)r0 * Hc + c) = pack_bf(h0, h1);
                *(uint32_t*)(hlo + (size_t)r0 * Hc + c) = pack_bf(l0, l1);
                split_bf16(v10, &h0, &l0); split_bf16(v11, &h1, &l1);
                *(uint32_t*)(hhi + (size_t)(r0 + 8) * Hc + c) = pack_bf(h0, h1);
                *(uint32_t*)(hlo + (size_t)(r0 + 8) * Hc + c) = pack_bf(l0, l1);
            } else {
                *(float2*)(cOut + (size_t)r0 * Hc + c)       = make_float2(v00, v01);
                *(float2*)(cOut + (size_t)(r0 + 8) * Hc + c) = make_float2(v10, v11);
            }
        }
    }
}

// ------------------------------ level GEMM ----------------------------------
__global__ void __launch_bounds__(256, 1)
gemm_level(const __nv_bfloat16* __restrict__ Ahi, const __nv_bfloat16* __restrict__ Alo,
           const __nv_bfloat16* __restrict__ Bhi, const __nv_bfloat16* __restrict__ Blo,
           const float* __restrict__ bias, float* __restrict__ gates, int M)
{
    extern __shared__ char smem[];
    const uint32_t sbase = (smem_u32(smem) + 127) & ~127u;

    const int tid = threadIdx.x;
    const int wid = tid >> 5, lane = tid & 31;
    const int wm = wid >> 2, wn = wid & 3;
    const int g = lane >> 2, t2 = (lane & 3) << 1;
    const int bm = blockIdx.x * 128;
    const int ny = blockIdx.y;
    const int Kc = 4;                    // K = 256

    float acc[4][4][4];
    #pragma unroll
    for (int i = 0; i < 4; i++)
        #pragma unroll
        for (int j = 0; j < 4; j++)
            #pragma unroll
            for (int q = 0; q < 4; q++) acc[i][j][q] = 0.f;

    issue_chunk(sbase, 0, tid, Ahi, Alo, bm, 256, Bhi, Blo, ny * 128, 256);
    CP_COMMIT();
    issue_chunk(sbase, 1, tid, Ahi, Alo, bm, 256, Bhi, Blo, ny * 128, 256);
    CP_COMMIT();
    for (int ch = 0; ch < Kc; ch++) {
        if (ch + 1 < Kc) CP_WAIT1(); else CP_WAIT0();
        __syncthreads();
        if (ch + 2 < Kc) {
            issue_chunk(sbase, ch + 2, tid, Ahi, Alo, bm, 256, Bhi, Blo, ny * 128, 256);
            CP_COMMIT();
        }
        stage_compute(sbase + (uint32_t)(ch % 3) * STAGE, wm, wn, lane, acc);
    }

    #pragma unroll
    for (int am = 0; am < 4; am++) {
        int r0 = bm + wm * 64 + am * 16 + g;
        #pragma unroll
        for (int an = 0; an < 4; an++) {
            int c  = wn * 32 + an * 8 + t2;
            int gc = ny * 128 + c;
            float b0 = bias[gc], b1 = bias[gc + 1];
            *(float2*)(gates + (size_t)r0 * NGATE + gc)
                = make_float2(acc[am][an][0] + b0, acc[am][an][1] + b1);
            *(float2*)(gates + (size_t)(r0 + 8) * NGATE + gc)
                = make_float2(acc[am][an][2] + b0, acc[am][an][3] + b1);
        }
    }
}

// ------------------------------- LSTM cell ----------------------------------
__global__ void lstm_cell4(const float* __restrict__ gates,
                           const float* __restrict__ c_prev,
                           __nv_bfloat16* __restrict__ hhi, __nv_bfloat16* __restrict__ hlo,
                           float* __restrict__ c_out, int M)
{
    int idx = blockIdx.x * blockDim.x + threadIdx.x;
    if (idx >= M * 32) return;
    int r = idx >> 5, j = (idx & 31) << 2;
    const float* g = gates + (size_t)r * NGATE;
    float4 i4  = *(const float4*)(g + j);
    float4 fl4 = *(const float4*)(g + 128 + j);
    float4 fr4 = *(const float4*)(g + 256 + j);
    float4 o4  = *(const float4*)(g + 384 + j);
    float4 g4  = *(const float4*)(g + 512 + j);
    const float* cp = c_prev + (size_t)r * 256;
    float4 cl4 = *(const float4*)(cp + j);
    float4 cr4 = *(const float4*)(cp + 128 + j);
    float4 c, h;
#define CEL(X) { float ii = sigf(i4.X), fl = sigf(fl4.X), fr = sigf(fr4.X);      \
                 float oo = sigf(o4.X), gg = tanhf(g4.X);                        \
                 float cc = fl * cl4.X + fr * cr4.X + ii * gg;                   \
                 c.X = cc; h.X = oo * tanhf(cc); }
    CEL(x) CEL(y) CEL(z) CEL(w)
#undef CEL
    *(float4*)(c_out + (size_t)r * Hc + j) = c;
    __nv_bfloat16 b0, l0, b1, l1, b2, l2, b3, l3;
    split_bf16(h.x, &b0, &l0); split_bf16(h.y, &b1, &l1);
    split_bf16(h.z, &b2, &l2); split_bf16(h.w, &b3, &l3);
    *(uint2*)(hhi + (size_t)r * Hc + j) = make_uint2(pack_bf(b0, b1), pack_bf(b2, b3));
    *(uint2*)(hlo + (size_t)r * Hc + j) = make_uint2(pack_bf(l0, l1), pack_bf(l2, l3));
}

// --------------------- fused tiny-level kernel (M <= 128) -------------------
#define RSM 4
__global__ void __launch_bounds__(640)
level_small(const __nv_bfloat16* __restrict__ Ahi, const __nv_bfloat16* __restrict__ Alo,
            const float* __restrict__ Wf, const float* __restrict__ bg,
            const float* __restrict__ c_prev,
            __nv_bfloat16* __restrict__ hhi_o, __nv_bfloat16* __restrict__ hlo_o,
            float* __restrict__ c_out, float* __restrict__ hf_out, int M)
{
    __shared__ float hs[RSM][256];
    __shared__ float gs[RSM][NGATE];
    const int tid = threadIdx.x;
    const int r0 = blockIdx.x * RSM;

    for (int idx = tid; idx < RSM * 256; idx += 640) {
        int r = idx >> 8, k = idx & 255;
        int gr = r0 + r;
        float v = 0.f;
        if (gr < M)
            v = __bfloat162float(Ahi[(size_t)gr * 256 + k])
              + __bfloat162float(Alo[(size_t)gr * 256 + k]);
        hs[r][k] = v;
    }
    __syncthreads();

    {
        const int c = tid;
        float a0 = 0.f, a1 = 0.f, a2 = 0.f, a3 = 0.f;
        #pragma unroll 4
        for (int k = 0; k < 256; k++) {
            float w = Wf[k * NGATE + c];
            a0 += hs[0][k] * w; a1 += hs[1][k] * w;
            a2 += hs[2][k] * w; a3 += hs[3][k] * w;
        }
        float b = bg[c];
        gs[0][c] = a0 + b; gs[1][c] = a1 + b; gs[2][c] = a2 + b; gs[3][c] = a3 + b;
    }
    __syncthreads();

    if (tid < RSM * 128) {
        int r = tid >> 7, u = tid & 127;
        int gr = r0 + r;
        if (gr < M) {
            float gi = sigf(gs[r][u]);
            float fl = sigf(gs[r][128 + u]);
            float fr = sigf(gs[r][256 + u]);
            float go = sigf(gs[r][384 + u]);
            float gg = tanhf(gs[r][512 + u]);
            float cl = c_prev[(size_t)gr * 256 + u];
            float cr = c_prev[(size_t)gr * 256 + 128 + u];
            float cc = fl * cl + fr * cr + gi * gg;
            float hh = go * tanhf(cc);
            c_out[(size_t)gr * Hc + u] = cc;
            if (hf_out) {
                hf_out[(size_t)gr * Hc + u] = hh;
            } else {
                __nv_bfloat16 hb, lb;
                split_bf16(hh, &hb, &lb);
                hhi_o[(size_t)gr * Hc + u] = hb;
                hlo_o[(size_t)gr * Hc + u] = lb;
            }
        }
    }
}

// --------------------------------- launch -----------------------------------
extern "C" void kernel_launch(void* const* d_in, const int* in_sizes, int n_in,
                              void* d_out, int out_size)
{
    const float* x      = (const float*)d_in[0];
    const float* W_leaf = (const float*)d_in[1];
    const float* b_leaf = (const float*)d_in[2];
    const float* W_l    = (const float*)d_in[3];
    const float* W_r    = (const float*)d_in[4];
    const float* bg     = (const float*)d_in[5];

    const int twoH = in_sizes[2];            // 256
    const int H    = twoH / 2;               // 128
    const int D    = in_sizes[1] / twoH;     // 300
    const int BL   = in_sizes[0] / D;        // 32768
    const int B    = out_size / H;           // 8
    const int L    = BL / B;                 // 4096
    int levels = 0;
    for (int t = L; t > 1; t >>= 1) levels++;

    __nv_bfloat16 *xhi, *xlo, *hhiA, *hloA, *hhiB, *hloB, *Wt_hi, *Wt_lo, *Wlf_hi, *Wlf_lo;
    float *cA, *cB, *gates, *Wstf;
    cudaGetSymbolAddress((void**)&xhi,    g_xhi);
    cudaGetSymbolAddress((void**)&xlo,    g_xlo);
    cudaGetSymbolAddress((void**)&hhiA,   g_hhiA);
    cudaGetSymbolAddress((void**)&hloA,   g_hloA);
    cudaGetSymbolAddress((void**)&hhiB,   g_hhiB);
    cudaGetSymbolAddress((void**)&hloB,   g_hloB);
    cudaGetSymbolAddress((void**)&cA,     g_cA);
    cudaGetSymbolAddress((void**)&cB,     g_cB);
    cudaGetSymbolAddress((void**)&gates,  g_gates);
    cudaGetSymbolAddress((void**)&Wstf,   g_Wstf);
    cudaGetSymbolAddress((void**)&Wt_hi,  g_Wt_hi);
    cudaGetSymbolAddress((void**)&Wt_lo,  g_Wt_lo);
    cudaGetSymbolAddress((void**)&Wlf_hi, g_WlfT_hi);
    cudaGetSymbolAddress((void**)&Wlf_lo, g_WlfT_lo);

    cudaFuncSetAttribute(gemm_leaf,  cudaFuncAttributeMaxDynamicSharedMemorySize, SMEM_REQ);
    cudaFuncSetAttribute(gemm_level, cudaFuncAttributeMaxDynamicSharedMemorySize, SMEM_REQ);

    // 1) prep
    prep_wst  <<<(NGATE * 256 + 255) / 256, 256>>>(W_l, W_r, Wt_hi, Wt_lo, Wstf);
    prep_wleaf<<<(256 * KB_LEAF + 255) / 256, 256>>>(W_leaf, Wlf_hi, Wlf_lo);
    split_x   <<<(BL * 80 + 255) / 256, 256>>>(x, xhi, xlo, BL, D);

    // 2) leaf GEMM
    {
        dim3 grid(BL / 128, 2);
        gemm_leaf<<<grid, 256, SMEM_REQ>>>(xhi, xlo, Wlf_hi, Wlf_lo, b_leaf,
                                           hhiA, hloA, cA, BL);
    }

    // 3) reduction levels
    __nv_bfloat16 *sh_hi = hhiA, *sh_lo = hloA, *dh_hi = hhiB, *dh_lo = hloB;
    float *sc = cA, *dc = cB;
    int n = L;
    for (int lvl = 0; lvl < levels; lvl++) {
        n >>= 1;
        int M = B * n;
        bool last = (lvl == levels - 1);

        if (M >= 256) {
            dim3 grid(M / 128, 5);
            gemm_level<<<grid, 256, SMEM_REQ>>>(sh_hi, sh_lo, Wt_hi, Wt_lo, bg, gates, M);
            lstm_cell4<<<(M * 32 + 255) / 256, 256>>>(gates, sc, dh_hi, dh_lo, dc, M);
        } else {
            level_small<<<(M + RSM - 1) / RSM, 640>>>(sh_hi, sh_lo, Wstf, bg, sc,
                                                      dh_hi, dh_lo, dc,
                                                      last ? (float*)d_out : nullptr, M);
        }

        __nv_bfloat16* t;
        t = sh_hi; sh_hi = dh_hi; dh_hi = t;
        t = sh_lo; sh_lo = dh_lo; dh_lo = t;
        float* tc = sc; sc = dc; dc = tc;
    }
}

// round 7
// speedup vs baseline: 1.0636x; 1.0636x over previous
#include <cuda_runtime.h>
#include <cuda_bf16.h>
#include <math.h>
#include <stdint.h>

// ---------------------------------------------------------------------------
// TreeLSTM on GB300, mma.sync bf16x3 (tcgen05 feature-gated off on this
// harness's compute_103 target).
// R7: 512-thread CTAs (16 warps, 4x4 warp grid, 32x32 warp tile) to cover
// HMMA latency; product-major MMA ordering (8 independent MMAs between
// accumulator reuses). 3-stage cp.async pipeline, ldmatrix fragment loads.
// D = Ah*Bh + Ah*Bl + Al*Bh, fp32 accumulators.
// ---------------------------------------------------------------------------

#define Hc      128
#define MAXBL   32768
#define NGATE   640
#define KB_LEAF 320
#define NTHR    512

__device__ __align__(128) __nv_bfloat16 g_xhi[MAXBL * KB_LEAF];
__device__ __align__(128) __nv_bfloat16 g_xlo[MAXBL * KB_LEAF];
__device__ __align__(128) __nv_bfloat16 g_hhiA[MAXBL * Hc];
__device__ __align__(128) __nv_bfloat16 g_hloA[MAXBL * Hc];
__device__ __align__(128) __nv_bfloat16 g_hhiB[(MAXBL / 2) * Hc];
__device__ __align__(128) __nv_bfloat16 g_hloB[(MAXBL / 2) * Hc];
__device__ float g_cA[MAXBL * Hc];
__device__ float g_cB[(MAXBL / 2) * Hc];
__device__ float g_gates[(MAXBL / 2) * NGATE];
__device__ __align__(128) __nv_bfloat16 g_Wt_hi[NGATE * 256];     // [640,256] K-major
__device__ __align__(128) __nv_bfloat16 g_Wt_lo[NGATE * 256];
__device__ float g_Wstf[256 * NGATE];                             // [256,640] fp32
__device__ __align__(128) __nv_bfloat16 g_WlfT_hi[256 * KB_LEAF]; // [256,320]
__device__ __align__(128) __nv_bfloat16 g_WlfT_lo[256 * KB_LEAF];

// ------------------------------- helpers -----------------------------------
__device__ __forceinline__ uint32_t smem_u32(const void* p) {
    uint32_t a;
    asm("{ .reg .u64 t; cvta.to.shared.u64 t, %1; cvt.u32.u64 %0, t; }"
        : "=r"(a) : "l"(p));
    return a;
}
#define CP_ASYNC16(dst, src) \
    asm volatile("cp.async.cg.shared.global [%0], [%1], 16;" \
                 :: "r"(dst), "l"(src) : "memory")
#define CP_COMMIT() asm volatile("cp.async.commit_group;" ::: "memory")
#define CP_WAIT1()  asm volatile("cp.async.wait_group 1;"  ::: "memory")
#define CP_WAIT0()  asm volatile("cp.async.wait_group 0;"  ::: "memory")

#define MMA16816(c, a, b)                                                      \
    asm volatile("mma.sync.aligned.m16n8k16.row.col.f32.bf16.bf16.f32 "       \
        "{%0,%1,%2,%3},{%4,%5,%6,%7},{%8,%9},{%0,%1,%2,%3};"                  \
        : "+f"((c)[0]), "+f"((c)[1]), "+f"((c)[2]), "+f"((c)[3])              \
        : "r"((a)[0]), "r"((a)[1]), "r"((a)[2]), "r"((a)[3]),                 \
          "r"((b)[0]), "r"((b)[1]))

__device__ __forceinline__ void ldsm4(uint32_t a, uint32_t& r0, uint32_t& r1,
                                      uint32_t& r2, uint32_t& r3) {
    asm volatile("ldmatrix.sync.aligned.m8n8.x4.shared.b16 {%0,%1,%2,%3}, [%4];"
                 : "=r"(r0), "=r"(r1), "=r"(r2), "=r"(r3) : "r"(a));
}

__device__ __forceinline__ void split_bf16(float w, __nv_bfloat16* hi, __nv_bfloat16* lo) {
    __nv_bfloat16 h = __float2bfloat16(w);
    *hi = h;
    *lo = __float2bfloat16(w - __bfloat162float(h));
}
__device__ __forceinline__ uint32_t pack_bf(__nv_bfloat16 a, __nv_bfloat16 b) {
    __nv_bfloat162 t{a, b};
    return *(uint32_t*)&t;
}
__device__ __forceinline__ float sigf(float x) { return 1.0f / (1.0f + expf(-x)); }

// Stage layout: A_hi | A_lo | B_hi | B_lo, each 128 rows x 128 bytes, swizzled.
#define TILE_B   16384
#define STAGE    65536
#define SMEM_REQ (3 * STAGE + 128)

// One 64-K chunk per stage: 4 k-steps; warp tile 32x32 (am 0..1, an 0..3).
// Product-major MMA order for independent-MMA bursts.
__device__ __forceinline__ void stage_compute(uint32_t st, int wm, int wn, int lane,
                                              float (*acc)[4][4])
{
    const int ts = lane >> 3, rs = lane & 7;
    const uint32_t Ah = st, Al = st + TILE_B, Bh = st + 2 * TILE_B, Bl = st + 3 * TILE_B;
    const int arow = wm * 32 + ((ts & 1) << 3) + rs;   // + am*16
    const int ach  = ts >> 1;
    const int brow = wn * 32 + ((ts >> 1) << 3) + rs;  // + j*16
    const int bch  = ts & 1;
    #pragma unroll
    for (int kk = 0; kk < 4; kk++) {
        uint32_t ah[2][4], al[2][4], bh[4][2], bl[4][2];
        #pragma unroll
        for (int am = 0; am < 2; am++) {
            uint32_t off = (uint32_t)((arow + am * 16) * 128)
                         + (((uint32_t)((kk * 2 + ach) ^ rs)) << 4);
            ldsm4(Ah + off, ah[am][0], ah[am][1], ah[am][2], ah[am][3]);
            ldsm4(Al + off, al[am][0], al[am][1], al[am][2], al[am][3]);
        }
        #pragma unroll
        for (int j = 0; j < 2; j++) {
            uint32_t off = (uint32_t)((brow + j * 16) * 128)
                         + (((uint32_t)((kk * 2 + bch) ^ rs)) << 4);
            ldsm4(Bh + off, bh[2*j][0], bh[2*j][1], bh[2*j+1][0], bh[2*j+1][1]);
            ldsm4(Bl + off, bl[2*j][0], bl[2*j][1], bl[2*j+1][0], bl[2*j+1][1]);
        }
        // product-major: 8 independent MMAs per pass
        #pragma unroll
        for (int am = 0; am < 2; am++)
            #pragma unroll
            for (int an = 0; an < 4; an++)
                MMA16816(acc[am][an], ah[am], bh[an]);
        #pragma unroll
        for (int am = 0; am < 2; am++)
            #pragma unroll
            for (int an = 0; an < 4; an++)
                MMA16816(acc[am][an], ah[am], bl[an]);
        #pragma unroll
        for (int am = 0; am < 2; am++)
            #pragma unroll
            for (int an = 0; an < 4; an++)
                MMA16816(acc[am][an], al[am], bh[an]);
    }
}

// Issue one 64-K chunk of A/B hi+lo tiles into stage (ch%3). 512 threads.
__device__ __forceinline__ void issue_chunk(uint32_t sbase, int ch, int tid,
                                            const __nv_bfloat16* Ahi, const __nv_bfloat16* Alo,
                                            int arow0, int aKB,
                                            const __nv_bfloat16* Bhi, const __nv_bfloat16* Blo,
                                            int brow0, int bKB)
{
    uint32_t st = sbase + (uint32_t)(ch % 3) * STAGE;
    #pragma unroll
    for (int i = 0; i < 8; i++) {
        int e = tid + i * NTHR;
        int mat = e >> 10;                     // uniform per i: 0:Ahi 1:Alo 2:Bhi 3:Blo
        int rem = e & 1023;
        int row = rem >> 3, chunk = rem & 7;
        const __nv_bfloat16* src;
        if (mat == 0)      src = Ahi + (size_t)(arow0 + row) * aKB + ch * 64 + chunk * 8;
        else if (mat == 1) src = Alo + (size_t)(arow0 + row) * aKB + ch * 64 + chunk * 8;
        else if (mat == 2) src = Bhi + (size_t)(brow0 + row) * bKB + ch * 64 + chunk * 8;
        else               src = Blo + (size_t)(brow0 + row) * bKB + ch * 64 + chunk * 8;
        uint32_t dst = st + mat * TILE_B + row * 128 + ((chunk ^ (row & 7)) << 4);
        CP_ASYNC16(dst, src);
    }
}

// ------------------------ weight / input prep ------------------------------
__global__ void prep_wst(const float* __restrict__ Wl, const float* __restrict__ Wr,
                         __nv_bfloat16* __restrict__ hi, __nv_bfloat16* __restrict__ lo,
                         float* __restrict__ Wf)
{
    int idx = blockIdx.x * blockDim.x + threadIdx.x;
    if (idx >= NGATE * 256) return;
    int n = idx >> 8, k = idx & 255;
    float w = (k < 128) ? Wl[k * NGATE + n] : Wr[(k - 128) * NGATE + n];
    split_bf16(w, &hi[idx], &lo[idx]);
    Wf[k * NGATE + n] = w;
}

__global__ void prep_wleaf(const float* __restrict__ W,
                           __nv_bfloat16* __restrict__ hi, __nv_bfloat16* __restrict__ lo)
{
    int idx = blockIdx.x * blockDim.x + threadIdx.x;
    if (idx >= 256 * KB_LEAF) return;
    int n = idx / KB_LEAF, k = idx % KB_LEAF;
    float w = (k < 300) ? W[k * 256 + n] : 0.0f;
    split_bf16(w, &hi[idx], &lo[idx]);
}

__global__ void split_x(const float* __restrict__ x,
                        __nv_bfloat16* __restrict__ xhi, __nv_bfloat16* __restrict__ xlo,
                        int BL, int D)
{
    int idx = blockIdx.x * blockDim.x + threadIdx.x;
    if (idx >= BL * 80) return;
    int row = idx / 80, k4 = (idx % 80) * 4;
    uint2 hv = make_uint2(0u, 0u), lv = hv;
    if (k4 < D) {
        float4 v = *(const float4*)(x + (size_t)row * D + k4);
        __nv_bfloat16 h0, l0, h1, l1, h2, l2, h3, l3;
        split_bf16(v.x, &h0, &l0); split_bf16(v.y, &h1, &l1);
        split_bf16(v.z, &h2, &l2); split_bf16(v.w, &h3, &l3);
        hv = make_uint2(pack_bf(h0, h1), pack_bf(h2, h3));
        lv = make_uint2(pack_bf(l0, l1), pack_bf(l2, l3));
    }
    *(uint2*)(xhi + (size_t)row * KB_LEAF + k4) = hv;
    *(uint2*)(xlo + (size_t)row * KB_LEAF + k4) = lv;
}

// ------------------------------ leaf GEMM -----------------------------------
__global__ void __launch_bounds__(NTHR, 1)
gemm_leaf(const __nv_bfloat16* __restrict__ Ahi, const __nv_bfloat16* __restrict__ Alo,
          const __nv_bfloat16* __restrict__ Bhi, const __nv_bfloat16* __restrict__ Blo,
          const float* __restrict__ bias,
          __nv_bfloat16* __restrict__ hhi, __nv_bfloat16* __restrict__ hlo,
          float* __restrict__ cOut, int M)
{
    extern __shared__ char smem[];
    const uint32_t sbase = (smem_u32(smem) + 127) & ~127u;

    const int tid = threadIdx.x;
    const int wid = tid >> 5, lane = tid & 31;
    const int wm = wid >> 2, wn = wid & 3;
    const int g = lane >> 2, t2 = (lane & 3) << 1;
    const int bm = blockIdx.x * 128;
    const int ny = blockIdx.y;
    const int Kc = KB_LEAF / 64;         // 5

    float acc[2][4][4];
    #pragma unroll
    for (int i = 0; i < 2; i++)
        #pragma unroll
        for (int j = 0; j < 4; j++)
            #pragma unroll
            for (int q = 0; q < 4; q++) acc[i][j][q] = 0.f;

    issue_chunk(sbase, 0, tid, Ahi, Alo, bm, KB_LEAF, Bhi, Blo, ny * 128, KB_LEAF);
    CP_COMMIT();
    issue_chunk(sbase, 1, tid, Ahi, Alo, bm, KB_LEAF, Bhi, Blo, ny * 128, KB_LEAF);
    CP_COMMIT();
    for (int ch = 0; ch < Kc; ch++) {
        if (ch + 1 < Kc) CP_WAIT1(); else CP_WAIT0();
        __syncthreads();
        if (ch + 2 < Kc) {
            issue_chunk(sbase, ch + 2, tid, Ahi, Alo, bm, KB_LEAF,
                        Bhi, Blo, ny * 128, KB_LEAF);
            CP_COMMIT();
        }
        stage_compute(sbase + (uint32_t)(ch % 3) * STAGE, wm, wn, lane, acc);
    }

    #pragma unroll
    for (int am = 0; am < 2; am++) {
        int r0 = bm + wm * 32 + am * 16 + g;
        #pragma unroll
        for (int an = 0; an < 4; an++) {
            int c  = wn * 32 + an * 8 + t2;
            float b0 = bias[ny * 128 + c], b1 = bias[ny * 128 + c + 1];
            float v00 = acc[am][an][0] + b0, v01 = acc[am][an][1] + b1;
            float v10 = acc[am][an][2] + b0, v11 = acc[am][an][3] + b1;
            if (ny == 0) {
                __nv_bfloat16 h0, l0, h1, l1;
                split_bf16(v00, &h0, &l0); split_bf16(v01, &h1, &l1);
                *(uint32_t*)(hhi + (size_t)r0 * Hc + c) = pack_bf(h0, h1);
                *(uint32_t*)(hlo + (size_t)r0 * Hc + c) = pack_bf(l0, l1);
                split_bf16(v10, &h0, &l0); split_bf16(v11, &h1, &l1);
                *(uint32_t*)(hhi + (size_t)(r0 + 8) * Hc + c) = pack_bf(h0, h1);
                *(uint32_t*)(hlo + (size_t)(r0 + 8) * Hc + c) = pack_bf(l0, l1);
            } else {
                *(float2*)(cOut + (size_t)r0 * Hc + c)       = make_float2(v00, v01);
                *(float2*)(cOut + (size_t)(r0 + 8) * Hc + c) = make_float2(v10, v11);
            }
        }
    }
}

// ------------------------------ level GEMM ----------------------------------
__global__ void __launch_bounds__(NTHR, 1)
gemm_level(const __nv_bfloat16* __restrict__ Ahi, const __nv_bfloat16* __restrict__ Alo,
           const __nv_bfloat16* __restrict__ Bhi, const __nv_bfloat16* __restrict__ Blo,
           const float* __restrict__ bias, float* __restrict__ gates, int M)
{
    extern __shared__ char smem[];
    const uint32_t sbase = (smem_u32(smem) + 127) & ~127u;

    const int tid = threadIdx.x;
    const int wid = tid >> 5, lane = tid & 31;
    const int wm = wid >> 2, wn = wid & 3;
    const int g = lane >> 2, t2 = (lane & 3) << 1;
    const int bm = blockIdx.x * 128;
    const int ny = blockIdx.y;
    const int Kc = 4;                    // K = 256

    float acc[2][4][4];
    #pragma unroll
    for (int i = 0; i < 2; i++)
        #pragma unroll
        for (int j = 0; j < 4; j++)
            #pragma unroll
            for (int q = 0; q < 4; q++) acc[i][j][q] = 0.f;

    issue_chunk(sbase, 0, tid, Ahi, Alo, bm, 256, Bhi, Blo, ny * 128, 256);
    CP_COMMIT();
    issue_chunk(sbase, 1, tid, Ahi, Alo, bm, 256, Bhi, Blo, ny * 128, 256);
    CP_COMMIT();
    for (int ch = 0; ch < Kc; ch++) {
        if (ch + 1 < Kc) CP_WAIT1(); else CP_WAIT0();
        __syncthreads();
        if (ch + 2 < Kc) {
            issue_chunk(sbase, ch + 2, tid, Ahi, Alo, bm, 256, Bhi, Blo, ny * 128, 256);
            CP_COMMIT();
        }
        stage_compute(sbase + (uint32_t)(ch % 3) * STAGE, wm, wn, lane, acc);
    }

    #pragma unroll
    for (int am = 0; am < 2; am++) {
        int r0 = bm + wm * 32 + am * 16 + g;
        #pragma unroll
        for (int an = 0; an < 4; an++) {
            int c  = wn * 32 + an * 8 + t2;
            int gc = ny * 128 + c;
            float b0 = bias[gc], b1 = bias[gc + 1];
            *(float2*)(gates + (size_t)r0 * NGATE + gc)
                = make_float2(acc[am][an][0] + b0, acc[am][an][1] + b1);
            *(float2*)(gates + (size_t)(r0 + 8) * NGATE + gc)
                = make_float2(acc[am][an][2] + b0, acc[am][an][3] + b1);
        }
    }
}

// ------------------------------- LSTM cell ----------------------------------
__global__ void lstm_cell4(const float* __restrict__ gates,
                           const float* __restrict__ c_prev,
                           __nv_bfloat16* __restrict__ hhi, __nv_bfloat16* __restrict__ hlo,
                           float* __restrict__ c_out, int M)
{
    int idx = blockIdx.x * blockDim.x + threadIdx.x;
    if (idx >= M * 32) return;
    int r = idx >> 5, j = (idx & 31) << 2;
    const float* g = gates + (size_t)r * NGATE;
    float4 i4  = *(const float4*)(g + j);
    float4 fl4 = *(const float4*)(g + 128 + j);
    float4 fr4 = *(const float4*)(g + 256 + j);
    float4 o4  = *(const float4*)(g + 384 + j);
    float4 g4  = *(const float4*)(g + 512 + j);
    const float* cp = c_prev + (size_t)r * 256;
    float4 cl4 = *(const float4*)(cp + j);
    float4 cr4 = *(const float4*)(cp + 128 + j);
    float4 c, h;
#define CEL(X) { float ii = sigf(i4.X), fl = sigf(fl4.X), fr = sigf(fr4.X);      \
                 float oo = sigf(o4.X), gg = tanhf(g4.X);                        \
                 float cc = fl * cl4.X + fr * cr4.X + ii * gg;                   \
                 c.X = cc; h.X = oo * tanhf(cc); }
    CEL(x) CEL(y) CEL(z) CEL(w)
#undef CEL
    *(float4*)(c_out + (size_t)r * Hc + j) = c;
    __nv_bfloat16 b0, l0, b1, l1, b2, l2, b3, l3;
    split_bf16(h.x, &b0, &l0); split_bf16(h.y, &b1, &l1);
    split_bf16(h.z, &b2, &l2); split_bf16(h.w, &b3, &l3);
    *(uint2*)(hhi + (size_t)r * Hc + j) = make_uint2(pack_bf(b0, b1), pack_bf(b2, b3));
    *(uint2*)(hlo + (size_t)r * Hc + j) = make_uint2(pack_bf(l0, l1), pack_bf(l2, l3));
}

// --------------------- fused tiny-level kernel (M <= 128) -------------------
#define RSM 2
__global__ void __launch_bounds__(640)
level_small(const __nv_bfloat16* __restrict__ Ahi, const __nv_bfloat16* __restrict__ Alo,
            const float* __restrict__ Wf, const float* __restrict__ bg,
            const float* __restrict__ c_prev,
            __nv_bfloat16* __restrict__ hhi_o, __nv_bfloat16* __restrict__ hlo_o,
            float* __restrict__ c_out, float* __restrict__ hf_out, int M)
{
    __shared__ float hs[RSM][256];
    __shared__ float gs[RSM][NGATE];
    const int tid = threadIdx.x;
    const int r0 = blockIdx.x * RSM;

    for (int idx = tid; idx < RSM * 256; idx += 640) {
        int r = idx >> 8, k = idx & 255;
        int gr = r0 + r;
        float v = 0.f;
        if (gr < M)
            v = __bfloat162float(Ahi[(size_t)gr * 256 + k])
              + __bfloat162float(Alo[(size_t)gr * 256 + k]);
        hs[r][k] = v;
    }
    __syncthreads();

    {
        const int c = tid;
        float a0 = 0.f, a1 = 0.f;
        #pragma unroll 8
        for (int k = 0; k < 256; k++) {
            float w = Wf[k * NGATE + c];
            a0 += hs[0][k] * w; a1 += hs[1][k] * w;
        }
        float b = bg[c];
        gs[0][c] = a0 + b; gs[1][c] = a1 + b;
    }
    __syncthreads();

    if (tid < RSM * 128) {
        int r = tid >> 7, u = tid & 127;
        int gr = r0 + r;
        if (gr < M) {
            float gi = sigf(gs[r][u]);
            float fl = sigf(gs[r][128 + u]);
            float fr = sigf(gs[r][256 + u]);
            float go = sigf(gs[r][384 + u]);
            float gg = tanhf(gs[r][512 + u]);
            float cl = c_prev[(size_t)gr * 256 + u];
            float cr = c_prev[(size_t)gr * 256 + 128 + u];
            float cc = fl * cl + fr * cr + gi * gg;
            float hh = go * tanhf(cc);
            c_out[(size_t)gr * Hc + u] = cc;
            if (hf_out) {
                hf_out[(size_t)gr * Hc + u] = hh;
            } else {
                __nv_bfloat16 hb, lb;
                split_bf16(hh, &hb, &lb);
                hhi_o[(size_t)gr * Hc + u] = hb;
                hlo_o[(size_t)gr * Hc + u] = lb;
            }
        }
    }
}

// --------------------------------- launch -----------------------------------
extern "C" void kernel_launch(void* const* d_in, const int* in_sizes, int n_in,
                              void* d_out, int out_size)
{
    const float* x      = (const float*)d_in[0];
    const float* W_leaf = (const float*)d_in[1];
    const float* b_leaf = (const float*)d_in[2];
    const float* W_l    = (const float*)d_in[3];
    const float* W_r    = (const float*)d_in[4];
    const float* bg     = (const float*)d_in[5];

    const int twoH = in_sizes[2];            // 256
    const int H    = twoH / 2;               // 128
    const int D    = in_sizes[1] / twoH;     // 300
    const int BL   = in_sizes[0] / D;        // 32768
    const int B    = out_size / H;           // 8
    const int L    = BL / B;                 // 4096
    int levels = 0;
    for (int t = L; t > 1; t >>= 1) levels++;

    __nv_bfloat16 *xhi, *xlo, *hhiA, *hloA, *hhiB, *hloB, *Wt_hi, *Wt_lo, *Wlf_hi, *Wlf_lo;
    float *cA, *cB, *gates, *Wstf;
    cudaGetSymbolAddress((void**)&xhi,    g_xhi);
    cudaGetSymbolAddress((void**)&xlo,    g_xlo);
    cudaGetSymbolAddress((void**)&hhiA,   g_hhiA);
    cudaGetSymbolAddress((void**)&hloA,   g_hloA);
    cudaGetSymbolAddress((void**)&hhiB,   g_hhiB);
    cudaGetSymbolAddress((void**)&hloB,   g_hloB);
    cudaGetSymbolAddress((void**)&cA,     g_cA);
    cudaGetSymbolAddress((void**)&cB,     g_cB);
    cudaGetSymbolAddress((void**)&gates,  g_gates);
    cudaGetSymbolAddress((void**)&Wstf,   g_Wstf);
    cudaGetSymbolAddress((void**)&Wt_hi,  g_Wt_hi);
    cudaGetSymbolAddress((void**)&Wt_lo,  g_Wt_lo);
    cudaGetSymbolAddress((void**)&Wlf_hi, g_WlfT_hi);
    cudaGetSymbolAddress((void**)&Wlf_lo, g_WlfT_lo);

    cudaFuncSetAttribute(gemm_leaf,  cudaFuncAttributeMaxDynamicSharedMemorySize, SMEM_REQ);
    cudaFuncSetAttribute(gemm_level, cudaFuncAttributeMaxDynamicSharedMemorySize, SMEM_REQ);

    // 1) prep
    prep_wst  <<<(NGATE * 256 + 255) / 256, 256>>>(W_l, W_r, Wt_hi, Wt_lo, Wstf);
    prep_wleaf<<<(256 * KB_LEAF + 255) / 256, 256>>>(W_leaf, Wlf_hi, Wlf_lo);
    split_x   <<<(BL * 80 + 255) / 256, 256>>>(x, xhi, xlo, BL, D);

    // 2) leaf GEMM
    {
        dim3 grid(BL / 128, 2);
        gemm_leaf<<<grid, NTHR, SMEM_REQ>>>(xhi, xlo, Wlf_hi, Wlf_lo, b_leaf,
                                            hhiA, hloA, cA, BL);
    }

    // 3) reduction levels
    __nv_bfloat16 *sh_hi = hhiA, *sh_lo = hloA, *dh_hi = hhiB, *dh_lo = hloB;
    float *sc = cA, *dc = cB;
    int n = L;
    for (int lvl = 0; lvl < levels; lvl++) {
        n >>= 1;
        int M = B * n;
        bool last = (lvl == levels - 1);

        if (M >= 256) {
            dim3 grid(M / 128, 5);
            gemm_level<<<grid, NTHR, SMEM_REQ>>>(sh_hi, sh_lo, Wt_hi, Wt_lo, bg, gates, M);
            lstm_cell4<<<(M * 32 + 255) / 256, 256>>>(gates, sc, dh_hi, dh_lo, dc, M);
        } else {
            level_small<<<(M + RSM - 1) / RSM, 640>>>(sh_hi, sh_lo, Wstf, bg, sc,
                                                      dh_hi, dh_lo, dc,
                                                      last ? (float*)d_out : nullptr, M);
        }

        __nv_bfloat16* t;
        t = sh_hi; sh_hi = dh_hi; dh_hi = t;
        t = sh_lo; sh_lo = dh_lo; dh_lo = t;
        float* tc = sc; sc = dc; dc = tc;
    }
}

// round 8
// speedup vs baseline: 1.0658x; 1.0021x over previous
#include <cuda_runtime.h>
#include <cuda_bf16.h>
#include <math.h>
#include <stdint.h>

// ---------------------------------------------------------------------------
// TreeLSTM on GB300, mma.sync bf16x3 (tcgen05 feature-gated off on this
// harness's compute_103 target).
// R8: register-level fragment double-buffering (prefetch k-step kk+1 frags
// under kk's MMAs); leaf back to 256-thr 64x32 tile with in-kernel fp32->bf16
// A conversion (split_x removed); levels stay 512-thr 32x32 tile.
// D = Ah*Bh + Ah*Bl + Al*Bh, fp32 accumulators.
// ---------------------------------------------------------------------------

#define Hc      128
#define MAXBL   32768
#define NGATE   640
#define KB_LEAF 320
#define NTHR    512

__device__ __align__(128) __nv_bfloat16 g_hhiA[MAXBL * Hc];
__device__ __align__(128) __nv_bfloat16 g_hloA[MAXBL * Hc];
__device__ __align__(128) __nv_bfloat16 g_hhiB[(MAXBL / 2) * Hc];
__device__ __align__(128) __nv_bfloat16 g_hloB[(MAXBL / 2) * Hc];
__device__ float g_cA[MAXBL * Hc];
__device__ float g_cB[(MAXBL / 2) * Hc];
__device__ float g_gates[(MAXBL / 2) * NGATE];
__device__ __align__(128) __nv_bfloat16 g_Wt_hi[NGATE * 256];     // [640,256] K-major
__device__ __align__(128) __nv_bfloat16 g_Wt_lo[NGATE * 256];
__device__ float g_Wstf[256 * NGATE];                             // [256,640] fp32
__device__ __align__(128) __nv_bfloat16 g_WlfT_hi[256 * KB_LEAF]; // [256,320]
__device__ __align__(128) __nv_bfloat16 g_WlfT_lo[256 * KB_LEAF];

// ------------------------------- helpers -----------------------------------
__device__ __forceinline__ uint32_t smem_u32(const void* p) {
    uint32_t a;
    asm("{ .reg .u64 t; cvta.to.shared.u64 t, %1; cvt.u32.u64 %0, t; }"
        : "=r"(a) : "l"(p));
    return a;
}
#define CP_ASYNC16(dst, src) \
    asm volatile("cp.async.cg.shared.global [%0], [%1], 16;" \
                 :: "r"(dst), "l"(src) : "memory")
#define CP_COMMIT() asm volatile("cp.async.commit_group;" ::: "memory")
#define CP_WAIT1()  asm volatile("cp.async.wait_group 1;"  ::: "memory")
#define CP_WAIT0()  asm volatile("cp.async.wait_group 0;"  ::: "memory")

#define MMA16816(c, a, b)                                                      \
    asm volatile("mma.sync.aligned.m16n8k16.row.col.f32.bf16.bf16.f32 "       \
        "{%0,%1,%2,%3},{%4,%5,%6,%7},{%8,%9},{%0,%1,%2,%3};"                  \
        : "+f"((c)[0]), "+f"((c)[1]), "+f"((c)[2]), "+f"((c)[3])              \
        : "r"((a)[0]), "r"((a)[1]), "r"((a)[2]), "r"((a)[3]),                 \
          "r"((b)[0]), "r"((b)[1]))

__device__ __forceinline__ void ldsm4(uint32_t a, uint32_t& r0, uint32_t& r1,
                                      uint32_t& r2, uint32_t& r3) {
    asm volatile("ldmatrix.sync.aligned.m8n8.x4.shared.b16 {%0,%1,%2,%3}, [%4];"
                 : "=r"(r0), "=r"(r1), "=r"(r2), "=r"(r3) : "r"(a));
}

__device__ __forceinline__ void split_bf16(float w, __nv_bfloat16* hi, __nv_bfloat16* lo) {
    __nv_bfloat16 h = __float2bfloat16(w);
    *hi = h;
    *lo = __float2bfloat16(w - __bfloat162float(h));
}
__device__ __forceinline__ uint32_t pack_bf(__nv_bfloat16 a, __nv_bfloat16 b) {
    __nv_bfloat162 t{a, b};
    return *(uint32_t*)&t;
}
__device__ __forceinline__ float sigf(float x) { return 1.0f / (1.0f + expf(-x)); }

// Stage layout: A_hi | A_lo | B_hi | B_lo, each 128 rows x 128 bytes, swizzled.
#define TILE_B   16384
#define STAGE    65536
#define SMEM_REQ (3 * STAGE + 128)

// ---------------- fragments: 32x32 warp tile (level, 512 thr) ---------------
struct Frag32 { uint32_t ah[2][4], al[2][4], bh[4][2], bl[4][2]; };

__device__ __forceinline__ void ld_frags32(uint32_t st, int arow, int ach,
                                           int brow, int bch, int rs, int kk, Frag32& f)
{
    const uint32_t Ah = st, Al = st + TILE_B, Bh = st + 2 * TILE_B, Bl = st + 3 * TILE_B;
    #pragma unroll
    for (int am = 0; am < 2; am++) {
        uint32_t off = (uint32_t)((arow + am * 16) * 128)
                     + (((uint32_t)((kk * 2 + ach) ^ rs)) << 4);
        ldsm4(Ah + off, f.ah[am][0], f.ah[am][1], f.ah[am][2], f.ah[am][3]);
        ldsm4(Al + off, f.al[am][0], f.al[am][1], f.al[am][2], f.al[am][3]);
    }
    #pragma unroll
    for (int j = 0; j < 2; j++) {
        uint32_t off = (uint32_t)((brow + j * 16) * 128)
                     + (((uint32_t)((kk * 2 + bch) ^ rs)) << 4);
        ldsm4(Bh + off, f.bh[2*j][0], f.bh[2*j][1], f.bh[2*j+1][0], f.bh[2*j+1][1]);
        ldsm4(Bl + off, f.bl[2*j][0], f.bl[2*j][1], f.bl[2*j+1][0], f.bl[2*j+1][1]);
    }
}

__device__ __forceinline__ void mma_frag32(Frag32& f, float (*acc)[4][4]) {
    #pragma unroll
    for (int am = 0; am < 2; am++)
        #pragma unroll
        for (int an = 0; an < 4; an++)
            MMA16816(acc[am][an], f.ah[am], f.bh[an]);
    #pragma unroll
    for (int am = 0; am < 2; am++)
        #pragma unroll
        for (int an = 0; an < 4; an++)
            MMA16816(acc[am][an], f.ah[am], f.bl[an]);
    #pragma unroll
    for (int am = 0; am < 2; am++)
        #pragma unroll
        for (int an = 0; an < 4; an++)
            MMA16816(acc[am][an], f.al[am], f.bh[an]);
}

__device__ __forceinline__ void stage_compute32(uint32_t st, int wm, int wn, int lane,
                                                float (*acc)[4][4])
{
    const int ts = lane >> 3, rs = lane & 7;
    const int arow = wm * 32 + ((ts & 1) << 3) + rs;
    const int ach  = ts >> 1;
    const int brow = wn * 32 + ((ts >> 1) << 3) + rs;
    const int bch  = ts & 1;
    Frag32 f[2];
    ld_frags32(st, arow, ach, brow, bch, rs, 0, f[0]);
    #pragma unroll
    for (int kk = 0; kk < 4; kk++) {
        if (kk < 3) ld_frags32(st, arow, ach, brow, bch, rs, kk + 1, f[(kk + 1) & 1]);
        mma_frag32(f[kk & 1], acc);
    }
}

// ---------------- fragments: 64x32 warp tile (leaf, 256 thr) ----------------
struct Frag64 { uint32_t ah[4][4], al[4][4], bh[4][2], bl[4][2]; };

__device__ __forceinline__ void ld_frags64(uint32_t st, int arow, int ach,
                                           int brow, int bch, int rs, int kk, Frag64& f)
{
    const uint32_t Ah = st, Al = st + TILE_B, Bh = st + 2 * TILE_B, Bl = st + 3 * TILE_B;
    #pragma unroll
    for (int am = 0; am < 4; am++) {
        uint32_t off = (uint32_t)((arow + am * 16) * 128)
                     + (((uint32_t)((kk * 2 + ach) ^ rs)) << 4);
        ldsm4(Ah + off, f.ah[am][0], f.ah[am][1], f.ah[am][2], f.ah[am][3]);
        ldsm4(Al + off, f.al[am][0], f.al[am][1], f.al[am][2], f.al[am][3]);
    }
    #pragma unroll
    for (int j = 0; j < 2; j++) {
        uint32_t off = (uint32_t)((brow + j * 16) * 128)
                     + (((uint32_t)((kk * 2 + bch) ^ rs)) << 4);
        ldsm4(Bh + off, f.bh[2*j][0], f.bh[2*j][1], f.bh[2*j+1][0], f.bh[2*j+1][1]);
        ldsm4(Bl + off, f.bl[2*j][0], f.bl[2*j][1], f.bl[2*j+1][0], f.bl[2*j+1][1]);
    }
}

__device__ __forceinline__ void mma_frag64(Frag64& f, float (*acc)[4][4]) {
    #pragma unroll
    for (int am = 0; am < 4; am++)
        #pragma unroll
        for (int an = 0; an < 4; an++)
            MMA16816(acc[am][an], f.ah[am], f.bh[an]);
    #pragma unroll
    for (int am = 0; am < 4; am++)
        #pragma unroll
        for (int an = 0; an < 4; an++)
            MMA16816(acc[am][an], f.ah[am], f.bl[an]);
    #pragma unroll
    for (int am = 0; am < 4; am++)
        #pragma unroll
        for (int an = 0; an < 4; an++)
            MMA16816(acc[am][an], f.al[am], f.bh[an]);
}

__device__ __forceinline__ void stage_compute64(uint32_t st, int wm, int wn, int lane,
                                                float (*acc)[4][4])
{
    const int ts = lane >> 3, rs = lane & 7;
    const int arow = wm * 64 + ((ts & 1) << 3) + rs;
    const int ach  = ts >> 1;
    const int brow = wn * 32 + ((ts >> 1) << 3) + rs;
    const int bch  = ts & 1;
    Frag64 f[2];
    ld_frags64(st, arow, ach, brow, bch, rs, 0, f[0]);
    #pragma unroll
    for (int kk = 0; kk < 4; kk++) {
        if (kk < 3) ld_frags64(st, arow, ach, brow, bch, rs, kk + 1, f[(kk + 1) & 1]);
        mma_frag64(f[kk & 1], acc);
    }
}

// Issue one 64-K chunk of A/B hi+lo tiles into stage (ch%3). 512 threads.
__device__ __forceinline__ void issue_chunk(uint32_t sbase, int ch, int tid,
                                            const __nv_bfloat16* Ahi, const __nv_bfloat16* Alo,
                                            int arow0, int aKB,
                                            const __nv_bfloat16* Bhi, const __nv_bfloat16* Blo,
                                            int brow0, int bKB)
{
    uint32_t st = sbase + (uint32_t)(ch % 3) * STAGE;
    #pragma unroll
    for (int i = 0; i < 8; i++) {
        int e = tid + i * NTHR;
        int mat = e >> 10;
        int rem = e & 1023;
        int row = rem >> 3, chunk = rem & 7;
        const __nv_bfloat16* src;
        if (mat == 0)      src = Ahi + (size_t)(arow0 + row) * aKB + ch * 64 + chunk * 8;
        else if (mat == 1) src = Alo + (size_t)(arow0 + row) * aKB + ch * 64 + chunk * 8;
        else if (mat == 2) src = Bhi + (size_t)(brow0 + row) * bKB + ch * 64 + chunk * 8;
        else               src = Blo + (size_t)(brow0 + row) * bKB + ch * 64 + chunk * 8;
        uint32_t dst = st + mat * TILE_B + row * 128 + ((chunk ^ (row & 7)) << 4);
        CP_ASYNC16(dst, src);
    }
}

// ------------------------ weight prep (once/replay) ------------------------
__global__ void prep_wst(const float* __restrict__ Wl, const float* __restrict__ Wr,
                         __nv_bfloat16* __restrict__ hi, __nv_bfloat16* __restrict__ lo,
                         float* __restrict__ Wf)
{
    int idx = blockIdx.x * blockDim.x + threadIdx.x;
    if (idx >= NGATE * 256) return;
    int n = idx >> 8, k = idx & 255;
    float w = (k < 128) ? Wl[k * NGATE + n] : Wr[(k - 128) * NGATE + n];
    split_bf16(w, &hi[idx], &lo[idx]);
    Wf[k * NGATE + n] = w;
}

__global__ void prep_wleaf(const float* __restrict__ W,
                           __nv_bfloat16* __restrict__ hi, __nv_bfloat16* __restrict__ lo)
{
    int idx = blockIdx.x * blockDim.x + threadIdx.x;
    if (idx >= 256 * KB_LEAF) return;
    int n = idx / KB_LEAF, k = idx % KB_LEAF;
    float w = (k < 300) ? W[k * 256 + n] : 0.0f;
    split_bf16(w, &hi[idx], &lo[idx]);
}

// ------------------------------ leaf GEMM -----------------------------------
// hc = x @ W_leaf + b_leaf.  256 threads, 64x32 warp tile, A fp32 converted
// in-kernel (regs -> split -> smem), B pre-split via cp.async. 3-stage.
__global__ void __launch_bounds__(256, 1)
gemm_leaf(const float* __restrict__ A,
          const __nv_bfloat16* __restrict__ Bhi, const __nv_bfloat16* __restrict__ Blo,
          const float* __restrict__ bias,
          __nv_bfloat16* __restrict__ hhi, __nv_bfloat16* __restrict__ hlo,
          float* __restrict__ cOut, int M, int D)
{
    extern __shared__ char smem[];
    const uint32_t sb    = smem_u32(smem);
    const uint32_t sbase = (sb + 127) & ~127u;
    char* const tb = smem + (sbase - sb);

    const int tid = threadIdx.x;
    const int wid = tid >> 5, lane = tid & 31;
    const int wm = wid >> 2, wn = wid & 3;          // 2 x 4 warps
    const int g = lane >> 2, t2 = (lane & 3) << 1;
    const int bm = blockIdx.x * 128;
    const int ny = blockIdx.y;
    const int Kc = KB_LEAF / 64;                    // 5

    float acc[4][4][4];
    #pragma unroll
    for (int i = 0; i < 4; i++)
        #pragma unroll
        for (int j = 0; j < 4; j++)
            #pragma unroll
            for (int q = 0; q < 4; q++) acc[i][j][q] = 0.f;

    float4 aReg[8];

    auto issueB = [&](int ch) {
        uint32_t st = sbase + (uint32_t)(ch % 3) * STAGE + 2 * TILE_B;
        #pragma unroll
        for (int i = 0; i < 8; i++) {
            int e = tid + i * 256;                   // 0..2047
            int mat = e >> 10;                       // 0 hi, 1 lo
            int rem = e & 1023;
            int row = rem >> 3, chunk = rem & 7;
            const __nv_bfloat16* src = (mat ? Blo : Bhi)
                + (size_t)(ny * 128 + row) * KB_LEAF + ch * 64 + chunk * 8;
            uint32_t dst = st + mat * TILE_B + row * 128 + ((chunk ^ (row & 7)) << 4);
            CP_ASYNC16(dst, src);
        }
    };
    auto ldA = [&](int ch) {
        #pragma unroll
        for (int i = 0; i < 8; i++) {
            int f = tid + i * 256;
            int row = f >> 4, k4 = (f & 15) << 2;
            int k = ch * 64 + k4;
            float4 v = make_float4(0.f, 0.f, 0.f, 0.f);
            if (k < D) v = *(const float4*)(A + (size_t)(bm + row) * D + k);
            aReg[i] = v;
        }
    };
    auto stA = [&](int s) {
        char* st = tb + (s % 3) * STAGE;
        #pragma unroll
        for (int i = 0; i < 8; i++) {
            int f = tid + i * 256;
            int row = f >> 4, k4 = (f & 15) << 2;
            int chunk = k4 >> 3, half = (k4 >> 2) & 1;
            uint32_t off = row * 128 + ((chunk ^ (row & 7)) << 4) + half * 8;
            float4 v = aReg[i];
            __nv_bfloat16 h0, l0, h1, l1, h2, l2, h3, l3;
            split_bf16(v.x, &h0, &l0); split_bf16(v.y, &h1, &l1);
            split_bf16(v.z, &h2, &l2); split_bf16(v.w, &h3, &l3);
            *(uint2*)(st + off)          = make_uint2(pack_bf(h0, h1), pack_bf(h2, h3));
            *(uint2*)(st + TILE_B + off) = make_uint2(pack_bf(l0, l1), pack_bf(l2, l3));
        }
    };

    issueB(0); CP_COMMIT();
    ldA(0); stA(0);
    issueB(1); CP_COMMIT();
    ldA(1);
    for (int ch = 0; ch < Kc; ch++) {
        if (ch + 1 < Kc) CP_WAIT1(); else CP_WAIT0();
        __syncthreads();                              // stage ch (A stores + B cp.async) visible
        if (ch + 1 < Kc) stA(ch + 1);                 // A(ch+1) regs -> stage (ch+1)%3
        if (ch + 2 < Kc) { issueB(ch + 2); CP_COMMIT(); ldA(ch + 2); }
        stage_compute64(sbase + (uint32_t)(ch % 3) * STAGE, wm, wn, lane, acc);
    }

    #pragma unroll
    for (int am = 0; am < 4; am++) {
        int r0 = bm + wm * 64 + am * 16 + g;
        #pragma unroll
        for (int an = 0; an < 4; an++) {
            int c  = wn * 32 + an * 8 + t2;
            float b0 = bias[ny * 128 + c], b1 = bias[ny * 128 + c + 1];
            float v00 = acc[am][an][0] + b0, v01 = acc[am][an][1] + b1;
            float v10 = acc[am][an][2] + b0, v11 = acc[am][an][3] + b1;
            if (ny == 0) {
                __nv_bfloat16 h0, l0, h1, l1;
                split_bf16(v00, &h0, &l0); split_bf16(v01, &h1, &l1);
                *(uint32_t*)(hhi + (size_t)r0 * Hc + c) = pack_bf(h0, h1);
                *(uint32_t*)(hlo + (size_t)r0 * Hc + c) = pack_bf(l0, l1);
                split_bf16(v10, &h0, &l0); split_bf16(v11, &h1, &l1);
                *(uint32_t*)(hhi + (size_t)(r0 + 8) * Hc + c) = pack_bf(h0, h1);
                *(uint32_t*)(hlo + (size_t)(r0 + 8) * Hc + c) = pack_bf(l0, l1);
            } else {
                *(float2*)(cOut + (size_t)r0 * Hc + c)       = make_float2(v00, v01);
                *(float2*)(cOut + (size_t)(r0 + 8) * Hc + c) = make_float2(v10, v11);
            }
        }
    }
}

// ------------------------------ level GEMM ----------------------------------
__global__ void __launch_bounds__(NTHR, 1)
gemm_level(const __nv_bfloat16* __restrict__ Ahi, const __nv_bfloat16* __restrict__ Alo,
           const __nv_bfloat16* __restrict__ Bhi, const __nv_bfloat16* __restrict__ Blo,
           const float* __restrict__ bias, float* __restrict__ gates, int M)
{
    extern __shared__ char smem[];
    const uint32_t sbase = (smem_u32(smem) + 127) & ~127u;

    const int tid = threadIdx.x;
    const int wid = tid >> 5, lane = tid & 31;
    const int wm = wid >> 2, wn = wid & 3;           // 4 x 4 warps
    const int g = lane >> 2, t2 = (lane & 3) << 1;
    const int bm = blockIdx.x * 128;
    const int ny = blockIdx.y;
    const int Kc = 4;                                // K = 256

    float acc[2][4][4];
    #pragma unroll
    for (int i = 0; i < 2; i++)
        #pragma unroll
        for (int j = 0; j < 4; j++)
            #pragma unroll
            for (int q = 0; q < 4; q++) acc[i][j][q] = 0.f;

    issue_chunk(sbase, 0, tid, Ahi, Alo, bm, 256, Bhi, Blo, ny * 128, 256);
    CP_COMMIT();
    issue_chunk(sbase, 1, tid, Ahi, Alo, bm, 256, Bhi, Blo, ny * 128, 256);
    CP_COMMIT();
    for (int ch = 0; ch < Kc; ch++) {
        if (ch + 1 < Kc) CP_WAIT1(); else CP_WAIT0();
        __syncthreads();
        if (ch + 2 < Kc) {
            issue_chunk(sbase, ch + 2, tid, Ahi, Alo, bm, 256, Bhi, Blo, ny * 128, 256);
            CP_COMMIT();
        }
        stage_compute32(sbase + (uint32_t)(ch % 3) * STAGE, wm, wn, lane, acc);
    }

    #pragma unroll
    for (int am = 0; am < 2; am++) {
        int r0 = bm + wm * 32 + am * 16 + g;
        #pragma unroll
        for (int an = 0; an < 4; an++) {
            int c  = wn * 32 + an * 8 + t2;
            int gc = ny * 128 + c;
            float b0 = bias[gc], b1 = bias[gc + 1];
            *(float2*)(gates + (size_t)r0 * NGATE + gc)
                = make_float2(acc[am][an][0] + b0, acc[am][an][1] + b1);
            *(float2*)(gates + (size_t)(r0 + 8) * NGATE + gc)
                = make_float2(acc[am][an][2] + b0, acc[am][an][3] + b1);
        }
    }
}

// ------------------------------- LSTM cell ----------------------------------
__global__ void lstm_cell4(const float* __restrict__ gates,
                           const float* __restrict__ c_prev,
                           __nv_bfloat16* __restrict__ hhi, __nv_bfloat16* __restrict__ hlo,
                           float* __restrict__ c_out, int M)
{
    int idx = blockIdx.x * blockDim.x + threadIdx.x;
    if (idx >= M * 32) return;
    int r = idx >> 5, j = (idx & 31) << 2;
    const float* g = gates + (size_t)r * NGATE;
    float4 i4  = *(const float4*)(g + j);
    float4 fl4 = *(const float4*)(g + 128 + j);
    float4 fr4 = *(const float4*)(g + 256 + j);
    float4 o4  = *(const float4*)(g + 384 + j);
    float4 g4  = *(const float4*)(g + 512 + j);
    const float* cp = c_prev + (size_t)r * 256;
    float4 cl4 = *(const float4*)(cp + j);
    float4 cr4 = *(const float4*)(cp + 128 + j);
    float4 c, h;
#define CEL(X) { float ii = sigf(i4.X), fl = sigf(fl4.X), fr = sigf(fr4.X);      \
                 float oo = sigf(o4.X), gg = tanhf(g4.X);                        \
                 float cc = fl * cl4.X + fr * cr4.X + ii * gg;                   \
                 c.X = cc; h.X = oo * tanhf(cc); }
    CEL(x) CEL(y) CEL(z) CEL(w)
#undef CEL
    *(float4*)(c_out + (size_t)r * Hc + j) = c;
    __nv_bfloat16 b0, l0, b1, l1, b2, l2, b3, l3;
    split_bf16(h.x, &b0, &l0); split_bf16(h.y, &b1, &l1);
    split_bf16(h.z, &b2, &l2); split_bf16(h.w, &b3, &l3);
    *(uint2*)(hhi + (size_t)r * Hc + j) = make_uint2(pack_bf(b0, b1), pack_bf(b2, b3));
    *(uint2*)(hlo + (size_t)r * Hc + j) = make_uint2(pack_bf(l0, l1), pack_bf(l2, l3));
}

// --------------------- fused tiny-level kernel (M <= 128) -------------------
#define RSM 2
__global__ void __launch_bounds__(640)
level_small(const __nv_bfloat16* __restrict__ Ahi, const __nv_bfloat16* __restrict__ Alo,
            const float* __restrict__ Wf, const float* __restrict__ bg,
            const float* __restrict__ c_prev,
            __nv_bfloat16* __restrict__ hhi_o, __nv_bfloat16* __restrict__ hlo_o,
            float* __restrict__ c_out, float* __restrict__ hf_out, int M)
{
    __shared__ float hs[RSM][256];
    __shared__ float gs[RSM][NGATE];
    const int tid = threadIdx.x;
    const int r0 = blockIdx.x * RSM;

    for (int idx = tid; idx < RSM * 256; idx += 640) {
        int r = idx >> 8, k = idx & 255;
        int gr = r0 + r;
        float v = 0.f;
        if (gr < M)
            v = __bfloat162float(Ahi[(size_t)gr * 256 + k])
              + __bfloat162float(Alo[(size_t)gr * 256 + k]);
        hs[r][k] = v;
    }
    __syncthreads();

    {
        const int c = tid;
        float a0 = 0.f, a1 = 0.f;
        #pragma unroll 8
        for (int k = 0; k < 256; k++) {
            float w = Wf[k * NGATE + c];
            a0 += hs[0][k] * w; a1 += hs[1][k] * w;
        }
        float b = bg[c];
        gs[0][c] = a0 + b; gs[1][c] = a1 + b;
    }
    __syncthreads();

    if (tid < RSM * 128) {
        int r = tid >> 7, u = tid & 127;
        int gr = r0 + r;
        if (gr < M) {
            float gi = sigf(gs[r][u]);
            float fl = sigf(gs[r][128 + u]);
            float fr = sigf(gs[r][256 + u]);
            float go = sigf(gs[r][384 + u]);
            float gg = tanhf(gs[r][512 + u]);
            float cl = c_prev[(size_t)gr * 256 + u];
            float cr = c_prev[(size_t)gr * 256 + 128 + u];
            float cc = fl * cl + fr * cr + gi * gg;
            float hh = go * tanhf(cc);
            c_out[(size_t)gr * Hc + u] = cc;
            if (hf_out) {
                hf_out[(size_t)gr * Hc + u] = hh;
            } else {
                __nv_bfloat16 hb, lb;
                split_bf16(hh, &hb, &lb);
                hhi_o[(size_t)gr * Hc + u] = hb;
                hlo_o[(size_t)gr * Hc + u] = lb;
            }
        }
    }
}

// --------------------------------- launch -----------------------------------
extern "C" void kernel_launch(void* const* d_in, const int* in_sizes, int n_in,
                              void* d_out, int out_size)
{
    const float* x      = (const float*)d_in[0];
    const float* W_leaf = (const float*)d_in[1];
    const float* b_leaf = (const float*)d_in[2];
    const float* W_l    = (const float*)d_in[3];
    const float* W_r    = (const float*)d_in[4];
    const float* bg     = (const float*)d_in[5];

    const int twoH = in_sizes[2];            // 256
    const int H    = twoH / 2;               // 128
    const int D    = in_sizes[1] / twoH;     // 300
    const int BL   = in_sizes[0] / D;        // 32768
    const int B    = out_size / H;           // 8
    const int L    = BL / B;                 // 4096
    int levels = 0;
    for (int t = L; t > 1; t >>= 1) levels++;

    __nv_bfloat16 *hhiA, *hloA, *hhiB, *hloB, *Wt_hi, *Wt_lo, *Wlf_hi, *Wlf_lo;
    float *cA, *cB, *gates, *Wstf;
    cudaGetSymbolAddress((void**)&hhiA,   g_hhiA);
    cudaGetSymbolAddress((void**)&hloA,   g_hloA);
    cudaGetSymbolAddress((void**)&hhiB,   g_hhiB);
    cudaGetSymbolAddress((void**)&hloB,   g_hloB);
    cudaGetSymbolAddress((void**)&cA,     g_cA);
    cudaGetSymbolAddress((void**)&cB,     g_cB);
    cudaGetSymbolAddress((void**)&gates,  g_gates);
    cudaGetSymbolAddress((void**)&Wstf,   g_Wstf);
    cudaGetSymbolAddress((void**)&Wt_hi,  g_Wt_hi);
    cudaGetSymbolAddress((void**)&Wt_lo,  g_Wt_lo);
    cudaGetSymbolAddress((void**)&Wlf_hi, g_WlfT_hi);
    cudaGetSymbolAddress((void**)&Wlf_lo, g_WlfT_lo);

    cudaFuncSetAttribute(gemm_leaf,  cudaFuncAttributeMaxDynamicSharedMemorySize, SMEM_REQ);
    cudaFuncSetAttribute(gemm_level, cudaFuncAttributeMaxDynamicSharedMemorySize, SMEM_REQ);

    // 1) weight prep
    prep_wst  <<<(NGATE * 256 + 255) / 256, 256>>>(W_l, W_r, Wt_hi, Wt_lo, Wstf);
    prep_wleaf<<<(256 * KB_LEAF + 255) / 256, 256>>>(W_leaf, Wlf_hi, Wlf_lo);

    // 2) leaf GEMM (reads fp32 x directly, converts in-kernel)
    {
        dim3 grid(BL / 128, 2);
        gemm_leaf<<<grid, 256, SMEM_REQ>>>(x, Wlf_hi, Wlf_lo, b_leaf,
                                           hhiA, hloA, cA, BL, D);
    }

    // 3) reduction levels
    __nv_bfloat16 *sh_hi = hhiA, *sh_lo = hloA, *dh_hi = hhiB, *dh_lo = hloB;
    float *sc = cA, *dc = cB;
    int n = L;
    for (int lvl = 0; lvl < levels; lvl++) {
        n >>= 1;
        int M = B * n;
        bool last = (lvl == levels - 1);

        if (M >= 256) {
            dim3 grid(M / 128, 5);
            gemm_level<<<grid, NTHR, SMEM_REQ>>>(sh_hi, sh_lo, Wt_hi, Wt_lo, bg, gates, M);
            lstm_cell4<<<(M * 32 + 255) / 256, 256>>>(gates, sc, dh_hi, dh_lo, dc, M);
        } else {
            level_small<<<(M + RSM - 1) / RSM, 640>>>(sh_hi, sh_lo, Wstf, bg, sc,
                                                      dh_hi, dh_lo, dc,
                                                      last ? (float*)d_out : nullptr, M);
        }

        __nv_bfloat16* t;
        t = sh_hi; sh_hi = dh_hi; dh_hi = t;
        t = sh_lo; sh_lo = dh_lo; dh_lo = t;
        float* tc = sc; sc = dc; dc = tc;
    }
}

// round 9
// speedup vs baseline: 1.1367x; 1.0665x over previous
#include <cuda_runtime.h>
#include <cuda_bf16.h>
#include <math.h>
#include <stdint.h>

// ---------------------------------------------------------------------------
// TreeLSTM on GB300, mma.sync bf16x3 (tcgen05 feature-gated off on this
// harness's compute_103 target).
// R9: smem-crossbar-optimal geometry. 256 thr / 8 warps / 2x4 grid / 64x32
// warp tile (LDSM:tensor 2.0 vs 2.67), K-chunk 32 with 3-stage 96KB pipeline
// -> 2 CTAs/SM. Sequential-product fragment reuse keeps regs < 128.
// D = Ah*Bh + Ah*Bl + Al*Bh, fp32 accumulators.
// ---------------------------------------------------------------------------

#define Hc      128
#define MAXBL   32768
#define NGATE   640
#define KB_LEAF 320

__device__ __align__(128) __nv_bfloat16 g_hhiA[MAXBL * Hc];
__device__ __align__(128) __nv_bfloat16 g_hloA[MAXBL * Hc];
__device__ __align__(128) __nv_bfloat16 g_hhiB[(MAXBL / 2) * Hc];
__device__ __align__(128) __nv_bfloat16 g_hloB[(MAXBL / 2) * Hc];
__device__ float g_cA[MAXBL * Hc];
__device__ float g_cB[(MAXBL / 2) * Hc];
__device__ float g_gates[(MAXBL / 2) * NGATE];
__device__ __align__(128) __nv_bfloat16 g_Wt_hi[NGATE * 256];     // [640,256] K-major
__device__ __align__(128) __nv_bfloat16 g_Wt_lo[NGATE * 256];
__device__ float g_Wstf[256 * NGATE];                             // [256,640] fp32
__device__ __align__(128) __nv_bfloat16 g_WlfT_hi[256 * KB_LEAF]; // [256,320]
__device__ __align__(128) __nv_bfloat16 g_WlfT_lo[256 * KB_LEAF];

// ------------------------------- helpers -----------------------------------
__device__ __forceinline__ uint32_t smem_u32(const void* p) {
    uint32_t a;
    asm("{ .reg .u64 t; cvta.to.shared.u64 t, %1; cvt.u32.u64 %0, t; }"
        : "=r"(a) : "l"(p));
    return a;
}
#define CP_ASYNC16(dst, src) \
    asm volatile("cp.async.cg.shared.global [%0], [%1], 16;" \
                 :: "r"(dst), "l"(src) : "memory")
#define CP_COMMIT() asm volatile("cp.async.commit_group;" ::: "memory")
#define CP_WAIT1()  asm volatile("cp.async.wait_group 1;"  ::: "memory")
#define CP_WAIT0()  asm volatile("cp.async.wait_group 0;"  ::: "memory")

#define MMA16816(c, a, b)                                                      \
    asm volatile("mma.sync.aligned.m16n8k16.row.col.f32.bf16.bf16.f32 "       \
        "{%0,%1,%2,%3},{%4,%5,%6,%7},{%8,%9},{%0,%1,%2,%3};"                  \
        : "+f"((c)[0]), "+f"((c)[1]), "+f"((c)[2]), "+f"((c)[3])              \
        : "r"((a)[0]), "r"((a)[1]), "r"((a)[2]), "r"((a)[3]),                 \
          "r"((b)[0]), "r"((b)[1]))

__device__ __forceinline__ void ldsm4(uint32_t a, uint32_t& r0, uint32_t& r1,
                                      uint32_t& r2, uint32_t& r3) {
    asm volatile("ldmatrix.sync.aligned.m8n8.x4.shared.b16 {%0,%1,%2,%3}, [%4];"
                 : "=r"(r0), "=r"(r1), "=r"(r2), "=r"(r3) : "r"(a));
}

__device__ __forceinline__ void split_bf16(float w, __nv_bfloat16* hi, __nv_bfloat16* lo) {
    __nv_bfloat16 h = __float2bfloat16(w);
    *hi = h;
    *lo = __float2bfloat16(w - __bfloat162float(h));
}
__device__ __forceinline__ uint32_t pack_bf(__nv_bfloat16 a, __nv_bfloat16 b) {
    __nv_bfloat162 t{a, b};
    return *(uint32_t*)&t;
}
__device__ __forceinline__ float sigf(float x) { return 1.0f / (1.0f + expf(-x)); }

// Tiles: 128 rows x 32 k-cols bf16 = 64B/row, 8KB per matrix.
// Stage: A_hi | A_lo | B_hi | B_lo = 32KB. 3 stages = 96KB -> 2 CTAs/SM.
#define TILE_B   8192
#define STAGE    32768
#define SMEM_REQ (3 * STAGE)

// 64B-row swizzle: chunk (16B unit, 0..3) xor'd with (row>>1)&3.
// Conflict-free for 8-row LDSM phases and for row-major cp.async stores.
__device__ __forceinline__ uint32_t sw_off(int row, int chunk) {
    return (uint32_t)(row * 64 + ((chunk ^ ((row >> 1) & 3)) << 4));
}

// ---- compute one 32-K chunk: 2 k-steps; 64x32 warp tile (2x4 warp grid) ----
// Sequential products: load a_hi,b_hi,b_lo -> hh+hl MMAs -> overwrite a with
// a_lo -> lh MMAs. Peak frag regs ~32.
__device__ __forceinline__ void stage_compute(uint32_t st, int wm, int wn, int lane,
                                              float (*acc)[4][4])
{
    const int ts = lane >> 3, rs = lane & 7;
    const uint32_t Ah = st, Al = st + TILE_B, Bh = st + 2 * TILE_B, Bl = st + 3 * TILE_B;
    const int arow = wm * 64 + ((ts & 1) << 3) + rs;   // + am*16
    const int ach  = ts >> 1;
    const int brow = wn * 32 + ((ts >> 1) << 3) + rs;  // + j*16
    const int bch  = ts & 1;
    #pragma unroll
    for (int kk = 0; kk < 2; kk++) {
        uint32_t a[4][4], bh[4][2], bl[4][2];
        const int akc = kk * 2 + ach;
        const int bkc = kk * 2 + bch;
        // B fragments (hi+lo) and A_hi
        #pragma unroll
        for (int j = 0; j < 2; j++) {
            uint32_t off = sw_off(brow + j * 16, bkc);
            ldsm4(Bh + off, bh[2*j][0], bh[2*j][1], bh[2*j+1][0], bh[2*j+1][1]);
            ldsm4(Bl + off, bl[2*j][0], bl[2*j][1], bl[2*j+1][0], bl[2*j+1][1]);
        }
        #pragma unroll
        for (int am = 0; am < 4; am++) {
            uint32_t off = sw_off(arow + am * 16, akc);
            ldsm4(Ah + off, a[am][0], a[am][1], a[am][2], a[am][3]);
        }
        #pragma unroll
        for (int am = 0; am < 4; am++)
            #pragma unroll
            for (int an = 0; an < 4; an++)
                MMA16816(acc[am][an], a[am], bh[an]);
        #pragma unroll
        for (int am = 0; am < 4; am++)
            #pragma unroll
            for (int an = 0; an < 4; an++)
                MMA16816(acc[am][an], a[am], bl[an]);
        // A_lo overwrites A_hi registers
        #pragma unroll
        for (int am = 0; am < 4; am++) {
            uint32_t off = sw_off(arow + am * 16, akc);
            ldsm4(Al + off, a[am][0], a[am][1], a[am][2], a[am][3]);
        }
        #pragma unroll
        for (int am = 0; am < 4; am++)
            #pragma unroll
            for (int an = 0; an < 4; an++)
                MMA16816(acc[am][an], a[am], bh[an]);
    }
}

// Issue one 32-K chunk of A/B hi+lo tiles into stage (ch%3). 256 threads.
__device__ __forceinline__ void issue_chunk(uint32_t sbase, int ch, int tid,
                                            const __nv_bfloat16* Ahi, const __nv_bfloat16* Alo,
                                            int arow0, int aKB,
                                            const __nv_bfloat16* Bhi, const __nv_bfloat16* Blo,
                                            int brow0, int bKB)
{
    uint32_t st = sbase + (uint32_t)(ch % 3) * STAGE;
    #pragma unroll
    for (int i = 0; i < 8; i++) {
        int e = tid + i * 256;
        int mat = e >> 9;                      // 0:Ahi 1:Alo 2:Bhi 3:Blo
        int rem = e & 511;
        int row = rem >> 2, chunk = rem & 3;
        const __nv_bfloat16* src;
        if (mat == 0)      src = Ahi + (size_t)(arow0 + row) * aKB + ch * 32 + chunk * 8;
        else if (mat == 1) src = Alo + (size_t)(arow0 + row) * aKB + ch * 32 + chunk * 8;
        else if (mat == 2) src = Bhi + (size_t)(brow0 + row) * bKB + ch * 32 + chunk * 8;
        else               src = Blo + (size_t)(brow0 + row) * bKB + ch * 32 + chunk * 8;
        uint32_t dst = st + mat * TILE_B + sw_off(row, chunk);
        CP_ASYNC16(dst, src);
    }
}

// ------------------------ weight prep (once/replay) ------------------------
__global__ void prep_wst(const float* __restrict__ Wl, const float* __restrict__ Wr,
                         __nv_bfloat16* __restrict__ hi, __nv_bfloat16* __restrict__ lo,
                         float* __restrict__ Wf)
{
    int idx = blockIdx.x * blockDim.x + threadIdx.x;
    if (idx >= NGATE * 256) return;
    int n = idx >> 8, k = idx & 255;
    float w = (k < 128) ? Wl[k * NGATE + n] : Wr[(k - 128) * NGATE + n];
    split_bf16(w, &hi[idx], &lo[idx]);
    Wf[k * NGATE + n] = w;
}

__global__ void prep_wleaf(const float* __restrict__ W,
                           __nv_bfloat16* __restrict__ hi, __nv_bfloat16* __restrict__ lo)
{
    int idx = blockIdx.x * blockDim.x + threadIdx.x;
    if (idx >= 256 * KB_LEAF) return;
    int n = idx / KB_LEAF, k = idx % KB_LEAF;
    float w = (k < 300) ? W[k * 256 + n] : 0.0f;
    split_bf16(w, &hi[idx], &lo[idx]);
}

// ------------------------------ leaf GEMM -----------------------------------
// hc = x @ W_leaf + b_leaf. A fp32 converted in-kernel, B pre-split cp.async.
__global__ void __launch_bounds__(256, 2)
gemm_leaf(const float* __restrict__ A,
          const __nv_bfloat16* __restrict__ Bhi, const __nv_bfloat16* __restrict__ Blo,
          const float* __restrict__ bias,
          __nv_bfloat16* __restrict__ hhi, __nv_bfloat16* __restrict__ hlo,
          float* __restrict__ cOut, int M, int D)
{
    extern __shared__ char smem[];
    const uint32_t sbase = smem_u32(smem);
    char* const tb = smem;

    const int tid = threadIdx.x;
    const int wid = tid >> 5, lane = tid & 31;
    const int wm = wid >> 2, wn = wid & 3;          // 2 x 4 warps
    const int g = lane >> 2, t2 = (lane & 3) << 1;
    const int bm = blockIdx.x * 128;
    const int ny = blockIdx.y;
    const int Kc = KB_LEAF / 32;                    // 10

    float acc[4][4][4];
    #pragma unroll
    for (int i = 0; i < 4; i++)
        #pragma unroll
        for (int j = 0; j < 4; j++)
            #pragma unroll
            for (int q = 0; q < 4; q++) acc[i][j][q] = 0.f;

    float4 aReg[4];

    auto issueB = [&](int ch) {
        uint32_t st = sbase + (uint32_t)(ch % 3) * STAGE + 2 * TILE_B;
        #pragma unroll
        for (int i = 0; i < 4; i++) {
            int e = tid + i * 256;                   // 0..1023
            int mat = e >> 9;                        // 0 hi, 1 lo
            int rem = e & 511;
            int row = rem >> 2, chunk = rem & 3;
            const __nv_bfloat16* src = (mat ? Blo : Bhi)
                + (size_t)(ny * 128 + row) * KB_LEAF + ch * 32 + chunk * 8;
            uint32_t dst = st + mat * TILE_B + sw_off(row, chunk);
            CP_ASYNC16(dst, src);
        }
    };
    auto ldA = [&](int ch) {
        #pragma unroll
        for (int i = 0; i < 4; i++) {
            int f = tid + i * 256;                   // 0..1023 = 128 rows x 8 quads
            int row = f >> 3, k4 = (f & 7) << 2;
            int k = ch * 32 + k4;
            float4 v = make_float4(0.f, 0.f, 0.f, 0.f);
            if (k < D) v = *(const float4*)(A + (size_t)(bm + row) * D + k);
            aReg[i] = v;
        }
    };
    auto stA = [&](int s) {
        char* st = tb + (s % 3) * STAGE;
        #pragma unroll
        for (int i = 0; i < 4; i++) {
            int f = tid + i * 256;
            int row = f >> 3, k4 = (f & 7) << 2;
            int chunk = k4 >> 3, half = (k4 >> 2) & 1;
            uint32_t off = sw_off(row, chunk) + half * 8;
            float4 v = aReg[i];
            __nv_bfloat16 h0, l0, h1, l1, h2, l2, h3, l3;
            split_bf16(v.x, &h0, &l0); split_bf16(v.y, &h1, &l1);
            split_bf16(v.z, &h2, &l2); split_bf16(v.w, &h3, &l3);
            *(uint2*)(st + off)          = make_uint2(pack_bf(h0, h1), pack_bf(h2, h3));
            *(uint2*)(st + TILE_B + off) = make_uint2(pack_bf(l0, l1), pack_bf(l2, l3));
        }
    };

    issueB(0); CP_COMMIT();
    ldA(0); stA(0);
    issueB(1); CP_COMMIT();
    ldA(1);
    for (int ch = 0; ch < Kc; ch++) {
        if (ch + 1 < Kc) CP_WAIT1(); else CP_WAIT0();
        __syncthreads();                              // stage ch fully visible
        if (ch + 1 < Kc) stA(ch + 1);                 // into stage (ch+1)%3
        if (ch + 2 < Kc) { issueB(ch + 2); CP_COMMIT(); ldA(ch + 2); }
        stage_compute(sbase + (uint32_t)(ch % 3) * STAGE, wm, wn, lane, acc);
    }

    #pragma unroll
    for (int am = 0; am < 4; am++) {
        int r0 = bm + wm * 64 + am * 16 + g;
        #pragma unroll
        for (int an = 0; an < 4; an++) {
            int c  = wn * 32 + an * 8 + t2;
            float b0 = bias[ny * 128 + c], b1 = bias[ny * 128 + c + 1];
            float v00 = acc[am][an][0] + b0, v01 = acc[am][an][1] + b1;
            float v10 = acc[am][an][2] + b0, v11 = acc[am][an][3] + b1;
            if (ny == 0) {
                __nv_bfloat16 h0, l0, h1, l1;
                split_bf16(v00, &h0, &l0); split_bf16(v01, &h1, &l1);
                *(uint32_t*)(hhi + (size_t)r0 * Hc + c) = pack_bf(h0, h1);
                *(uint32_t*)(hlo + (size_t)r0 * Hc + c) = pack_bf(l0, l1);
                split_bf16(v10, &h0, &l0); split_bf16(v11, &h1, &l1);
                *(uint32_t*)(hhi + (size_t)(r0 + 8) * Hc + c) = pack_bf(h0, h1);
                *(uint32_t*)(hlo + (size_t)(r0 + 8) * Hc + c) = pack_bf(l0, l1);
            } else {
                *(float2*)(cOut + (size_t)r0 * Hc + c)       = make_float2(v00, v01);
                *(float2*)(cOut + (size_t)(r0 + 8) * Hc + c) = make_float2(v10, v11);
            }
        }
    }
}

// ------------------------------ level GEMM ----------------------------------
__global__ void __launch_bounds__(256, 2)
gemm_level(const __nv_bfloat16* __restrict__ Ahi, const __nv_bfloat16* __restrict__ Alo,
           const __nv_bfloat16* __restrict__ Bhi, const __nv_bfloat16* __restrict__ Blo,
           const float* __restrict__ bias, float* __restrict__ gates, int M)
{
    extern __shared__ char smem[];
    const uint32_t sbase = smem_u32(smem);

    const int tid = threadIdx.x;
    const int wid = tid >> 5, lane = tid & 31;
    const int wm = wid >> 2, wn = wid & 3;           // 2 x 4 warps
    const int g = lane >> 2, t2 = (lane & 3) << 1;
    const int bm = blockIdx.x * 128;
    const int ny = blockIdx.y;
    const int Kc = 8;                                // K = 256

    float acc[4][4][4];
    #pragma unroll
    for (int i = 0; i < 4; i++)
        #pragma unroll
        for (int j = 0; j < 4; j++)
            #pragma unroll
            for (int q = 0; q < 4; q++) acc[i][j][q] = 0.f;

    issue_chunk(sbase, 0, tid, Ahi, Alo, bm, 256, Bhi, Blo, ny * 128, 256);
    CP_COMMIT();
    issue_chunk(sbase, 1, tid, Ahi, Alo, bm, 256, Bhi, Blo, ny * 128, 256);
    CP_COMMIT();
    for (int ch = 0; ch < Kc; ch++) {
        if (ch + 1 < Kc) CP_WAIT1(); else CP_WAIT0();
        __syncthreads();
        if (ch + 2 < Kc) {
            issue_chunk(sbase, ch + 2, tid, Ahi, Alo, bm, 256, Bhi, Blo, ny * 128, 256);
            CP_COMMIT();
        }
        stage_compute(sbase + (uint32_t)(ch % 3) * STAGE, wm, wn, lane, acc);
    }

    #pragma unroll
    for (int am = 0; am < 4; am++) {
        int r0 = bm + wm * 64 + am * 16 + g;
        #pragma unroll
        for (int an = 0; an < 4; an++) {
            int c  = wn * 32 + an * 8 + t2;
            int gc = ny * 128 + c;
            float b0 = bias[gc], b1 = bias[gc + 1];
            *(float2*)(gates + (size_t)r0 * NGATE + gc)
                = make_float2(acc[am][an][0] + b0, acc[am][an][1] + b1);
            *(float2*)(gates + (size_t)(r0 + 8) * NGATE + gc)
                = make_float2(acc[am][an][2] + b0, acc[am][an][3] + b1);
        }
    }
}

// ------------------------------- LSTM cell ----------------------------------
__global__ void lstm_cell4(const float* __restrict__ gates,
                           const float* __restrict__ c_prev,
                           __nv_bfloat16* __restrict__ hhi, __nv_bfloat16* __restrict__ hlo,
                           float* __restrict__ c_out, int M)
{
    int idx = blockIdx.x * blockDim.x + threadIdx.x;
    if (idx >= M * 32) return;
    int r = idx >> 5, j = (idx & 31) << 2;
    const float* g = gates + (size_t)r * NGATE;
    float4 i4  = *(const float4*)(g + j);
    float4 fl4 = *(const float4*)(g + 128 + j);
    float4 fr4 = *(const float4*)(g + 256 + j);
    float4 o4  = *(const float4*)(g + 384 + j);
    float4 g4  = *(const float4*)(g + 512 + j);
    const float* cp = c_prev + (size_t)r * 256;
    float4 cl4 = *(const float4*)(cp + j);
    float4 cr4 = *(const float4*)(cp + 128 + j);
    float4 c, h;
#define CEL(X) { float ii = sigf(i4.X), fl = sigf(fl4.X), fr = sigf(fr4.X);      \
                 float oo = sigf(o4.X), gg = tanhf(g4.X);                        \
                 float cc = fl * cl4.X + fr * cr4.X + ii * gg;                   \
                 c.X = cc; h.X = oo * tanhf(cc); }
    CEL(x) CEL(y) CEL(z) CEL(w)
#undef CEL
    *(float4*)(c_out + (size_t)r * Hc + j) = c;
    __nv_bfloat16 b0, l0, b1, l1, b2, l2, b3, l3;
    split_bf16(h.x, &b0, &l0); split_bf16(h.y, &b1, &l1);
    split_bf16(h.z, &b2, &l2); split_bf16(h.w, &b3, &l3);
    *(uint2*)(hhi + (size_t)r * Hc + j) = make_uint2(pack_bf(b0, b1), pack_bf(b2, b3));
    *(uint2*)(hlo + (size_t)r * Hc + j) = make_uint2(pack_bf(l0, l1), pack_bf(l2, l3));
}

// --------------------- fused tiny-level kernel (M <= 128) -------------------
#define RSM 2
__global__ void __launch_bounds__(640)
level_small(const __nv_bfloat16* __restrict__ Ahi, const __nv_bfloat16* __restrict__ Alo,
            const float* __restrict__ Wf, const float* __restrict__ bg,
            const float* __restrict__ c_prev,
            __nv_bfloat16* __restrict__ hhi_o, __nv_bfloat16* __restrict__ hlo_o,
            float* __restrict__ c_out, float* __restrict__ hf_out, int M)
{
    __shared__ float hs[RSM][256];
    __shared__ float gs[RSM][NGATE];
    const int tid = threadIdx.x;
    const int r0 = blockIdx.x * RSM;

    for (int idx = tid; idx < RSM * 256; idx += 640) {
        int r = idx >> 8, k = idx & 255;
        int gr = r0 + r;
        float v = 0.f;
        if (gr < M)
            v = __bfloat162float(Ahi[(size_t)gr * 256 + k])
              + __bfloat162float(Alo[(size_t)gr * 256 + k]);
        hs[r][k] = v;
    }
    __syncthreads();

    {
        const int c = tid;
        float a0 = 0.f, a1 = 0.f;
        #pragma unroll 8
        for (int k = 0; k < 256; k++) {
            float w = Wf[k * NGATE + c];
            a0 += hs[0][k] * w; a1 += hs[1][k] * w;
        }
        float b = bg[c];
        gs[0][c] = a0 + b; gs[1][c] = a1 + b;
    }
    __syncthreads();

    if (tid < RSM * 128) {
        int r = tid >> 7, u = tid & 127;
        int gr = r0 + r;
        if (gr < M) {
            float gi = sigf(gs[r][u]);
            float fl = sigf(gs[r][128 + u]);
            float fr = sigf(gs[r][256 + u]);
            float go = sigf(gs[r][384 + u]);
            float gg = tanhf(gs[r][512 + u]);
            float cl = c_prev[(size_t)gr * 256 + u];
            float cr = c_prev[(size_t)gr * 256 + 128 + u];
            float cc = fl * cl + fr * cr + gi * gg;
            float hh = go * tanhf(cc);
            c_out[(size_t)gr * Hc + u] = cc;
            if (hf_out) {
                hf_out[(size_t)gr * Hc + u] = hh;
            } else {
                __nv_bfloat16 hb, lb;
                split_bf16(hh, &hb, &lb);
                hhi_o[(size_t)gr * Hc + u] = hb;
                hlo_o[(size_t)gr * Hc + u] = lb;
            }
        }
    }
}

// --------------------------------- launch -----------------------------------
extern "C" void kernel_launch(void* const* d_in, const int* in_sizes, int n_in,
                              void* d_out, int out_size)
{
    const float* x      = (const float*)d_in[0];
    const float* W_leaf = (const float*)d_in[1];
    const float* b_leaf = (const float*)d_in[2];
    const float* W_l    = (const float*)d_in[3];
    const float* W_r    = (const float*)d_in[4];
    const float* bg     = (const float*)d_in[5];

    const int twoH = in_sizes[2];            // 256
    const int H    = twoH / 2;               // 128
    const int D    = in_sizes[1] / twoH;     // 300
    const int BL   = in_sizes[0] / D;        // 32768
    const int B    = out_size / H;           // 8
    const int L    = BL / B;                 // 4096
    int levels = 0;
    for (int t = L; t > 1; t >>= 1) levels++;

    __nv_bfloat16 *hhiA, *hloA, *hhiB, *hloB, *Wt_hi, *Wt_lo, *Wlf_hi, *Wlf_lo;
    float *cA, *cB, *gates, *Wstf;
    cudaGetSymbolAddress((void**)&hhiA,   g_hhiA);
    cudaGetSymbolAddress((void**)&hloA,   g_hloA);
    cudaGetSymbolAddress((void**)&hhiB,   g_hhiB);
    cudaGetSymbolAddress((void**)&hloB,   g_hloB);
    cudaGetSymbolAddress((void**)&cA,     g_cA);
    cudaGetSymbolAddress((void**)&cB,     g_cB);
    cudaGetSymbolAddress((void**)&gates,  g_gates);
    cudaGetSymbolAddress((void**)&Wstf,   g_Wstf);
    cudaGetSymbolAddress((void**)&Wt_hi,  g_Wt_hi);
    cudaGetSymbolAddress((void**)&Wt_lo,  g_Wt_lo);
    cudaGetSymbolAddress((void**)&Wlf_hi, g_WlfT_hi);
    cudaGetSymbolAddress((void**)&Wlf_lo, g_WlfT_lo);

    cudaFuncSetAttribute(gemm_leaf,  cudaFuncAttributeMaxDynamicSharedMemorySize, SMEM_REQ);
    cudaFuncSetAttribute(gemm_level, cudaFuncAttributeMaxDynamicSharedMemorySize, SMEM_REQ);

    // 1) weight prep
    prep_wst  <<<(NGATE * 256 + 255) / 256, 256>>>(W_l, W_r, Wt_hi, Wt_lo, Wstf);
    prep_wleaf<<<(256 * KB_LEAF + 255) / 256, 256>>>(W_leaf, Wlf_hi, Wlf_lo);

    // 2) leaf GEMM (reads fp32 x directly, converts in-kernel)
    {
        dim3 grid(BL / 128, 2);
        gemm_leaf<<<grid, 256, SMEM_REQ>>>(x, Wlf_hi, Wlf_lo, b_leaf,
                                           hhiA, hloA, cA, BL, D);
    }

    // 3) reduction levels
    __nv_bfloat16 *sh_hi = hhiA, *sh_lo = hloA, *dh_hi = hhiB, *dh_lo = hloB;
    float *sc = cA, *dc = cB;
    int n = L;
    for (int lvl = 0; lvl < levels; lvl++) {
        n >>= 1;
        int M = B * n;
        bool last = (lvl == levels - 1);

        if (M >= 256) {
            dim3 grid(M / 128, 5);
            gemm_level<<<grid, 256, SMEM_REQ>>>(sh_hi, sh_lo, Wt_hi, Wt_lo, bg, gates, M);
            lstm_cell4<<<(M * 32 + 255) / 256, 256>>>(gates, sc, dh_hi, dh_lo, dc, M);
        } else {
            level_small<<<(M + RSM - 1) / RSM, 640>>>(sh_hi, sh_lo, Wstf, bg, sc,
                                                      dh_hi, dh_lo, dc,
                                                      last ? (float*)d_out : nullptr, M);
        }

        __nv_bfloat16* t;
        t = sh_hi; sh_hi = dh_hi; dh_hi = t;
        t = sh_lo; sh_lo = dh_lo; dh_lo = t;
        float* tc = sc; sc = dc; dc = tc;
    }
}

// round 10
// speedup vs baseline: 1.1858x; 1.0432x over previous
#include <cuda_runtime.h>
#include <cuda_bf16.h>
#include <math.h>
#include <stdint.h>

// ---------------------------------------------------------------------------
// TreeLSTM on GB300, mma.sync bf16x3 (tcgen05 feature-gated off on this
// harness's compute_103 target).
// R10: occupancy push. CTA tile 64x128 (8 warps, 2x4 grid of 32x32 tiles,
// acc=32 regs), 2-stage 48KB smem pipeline, launch_bounds(256,3) -> 3 CTAs/SM
// (24 resident warps) so LDSM and MMA phases of different CTAs overlap.
// D = Ah*Bh + Ah*Bl + Al*Bh, fp32 accumulators.
// ---------------------------------------------------------------------------

#define Hc      128
#define MAXBL   32768
#define NGATE   640
#define KB_LEAF 320

__device__ __align__(128) __nv_bfloat16 g_hhiA[MAXBL * Hc];
__device__ __align__(128) __nv_bfloat16 g_hloA[MAXBL * Hc];
__device__ __align__(128) __nv_bfloat16 g_hhiB[(MAXBL / 2) * Hc];
__device__ __align__(128) __nv_bfloat16 g_hloB[(MAXBL / 2) * Hc];
__device__ float g_cA[MAXBL * Hc];
__device__ float g_cB[(MAXBL / 2) * Hc];
__device__ float g_gates[(MAXBL / 2) * NGATE];
__device__ __align__(128) __nv_bfloat16 g_Wt_hi[NGATE * 256];     // [640,256] K-major
__device__ __align__(128) __nv_bfloat16 g_Wt_lo[NGATE * 256];
__device__ float g_Wstf[256 * NGATE];                             // [256,640] fp32
__device__ __align__(128) __nv_bfloat16 g_WlfT_hi[256 * KB_LEAF]; // [256,320]
__device__ __align__(128) __nv_bfloat16 g_WlfT_lo[256 * KB_LEAF];

// ------------------------------- helpers -----------------------------------
__device__ __forceinline__ uint32_t smem_u32(const void* p) {
    uint32_t a;
    asm("{ .reg .u64 t; cvta.to.shared.u64 t, %1; cvt.u32.u64 %0, t; }"
        : "=r"(a) : "l"(p));
    return a;
}
#define CP_ASYNC16(dst, src) \
    asm volatile("cp.async.cg.shared.global [%0], [%1], 16;" \
                 :: "r"(dst), "l"(src) : "memory")
#define CP_COMMIT() asm volatile("cp.async.commit_group;" ::: "memory")
#define CP_WAIT1()  asm volatile("cp.async.wait_group 1;"  ::: "memory")
#define CP_WAIT0()  asm volatile("cp.async.wait_group 0;"  ::: "memory")

#define MMA16816(c, a, b)                                                      \
    asm volatile("mma.sync.aligned.m16n8k16.row.col.f32.bf16.bf16.f32 "       \
        "{%0,%1,%2,%3},{%4,%5,%6,%7},{%8,%9},{%0,%1,%2,%3};"                  \
        : "+f"((c)[0]), "+f"((c)[1]), "+f"((c)[2]), "+f"((c)[3])              \
        : "r"((a)[0]), "r"((a)[1]), "r"((a)[2]), "r"((a)[3]),                 \
          "r"((b)[0]), "r"((b)[1]))

__device__ __forceinline__ void ldsm4(uint32_t a, uint32_t& r0, uint32_t& r1,
                                      uint32_t& r2, uint32_t& r3) {
    asm volatile("ldmatrix.sync.aligned.m8n8.x4.shared.b16 {%0,%1,%2,%3}, [%4];"
                 : "=r"(r0), "=r"(r1), "=r"(r2), "=r"(r3) : "r"(a));
}

__device__ __forceinline__ void split_bf16(float w, __nv_bfloat16* hi, __nv_bfloat16* lo) {
    __nv_bfloat16 h = __float2bfloat16(w);
    *hi = h;
    *lo = __float2bfloat16(w - __bfloat162float(h));
}
__device__ __forceinline__ uint32_t pack_bf(__nv_bfloat16 a, __nv_bfloat16 b) {
    __nv_bfloat162 t{a, b};
    return *(uint32_t*)&t;
}
__device__ __forceinline__ float sigf(float x) { return 1.0f / (1.0f + expf(-x)); }

// Tiles (K-chunk 32, 64B rows): A 64x32 bf16 = 4KB, B 128x32 bf16 = 8KB.
// Stage: A_hi | A_lo | B_hi | B_lo = 24KB. 2 stages = 48KB -> 3 CTAs/SM.
#define TILE_A   4096
#define TILE_Bb  8192
#define STAGE    24576
#define SMEM_REQ (2 * STAGE)

// 64B-row swizzle: 16B chunk xor'd with (row>>1)&3. Conflict-free for 8-row
// LDSM phases and row-major cp.async stores (verified R9).
__device__ __forceinline__ uint32_t sw_off(int row, int chunk) {
    return (uint32_t)(row * 64 + ((chunk ^ ((row >> 1) & 3)) << 4));
}

// ---- compute one 32-K chunk: 2 k-steps; 32x32 warp tile (2x4 warp grid) ----
// Sequential products: B hi/lo + A_hi -> hh+hl MMAs -> A_lo -> lh MMAs.
// Frag regs ~24, acc 32.
__device__ __forceinline__ void stage_compute(uint32_t st, int wm, int wn, int lane,
                                              float (*acc)[4][4])
{
    const int ts = lane >> 3, rs = lane & 7;
    const uint32_t Ah = st, Al = st + TILE_A;
    const uint32_t Bh = st + 2 * TILE_A, Bl = st + 2 * TILE_A + TILE_Bb;
    const int arow = wm * 32 + ((ts & 1) << 3) + rs;   // + am*16
    const int ach  = ts >> 1;
    const int brow = wn * 32 + ((ts >> 1) << 3) + rs;  // + j*16
    const int bch  = ts & 1;
    #pragma unroll
    for (int kk = 0; kk < 2; kk++) {
        uint32_t a[2][4], bh[4][2], bl[4][2];
        const int akc = kk * 2 + ach;
        const int bkc = kk * 2 + bch;
        #pragma unroll
        for (int j = 0; j < 2; j++) {
            uint32_t off = sw_off(brow + j * 16, bkc);
            ldsm4(Bh + off, bh[2*j][0], bh[2*j][1], bh[2*j+1][0], bh[2*j+1][1]);
            ldsm4(Bl + off, bl[2*j][0], bl[2*j][1], bl[2*j+1][0], bl[2*j+1][1]);
        }
        #pragma unroll
        for (int am = 0; am < 2; am++) {
            uint32_t off = sw_off(arow + am * 16, akc);
            ldsm4(Ah + off, a[am][0], a[am][1], a[am][2], a[am][3]);
        }
        #pragma unroll
        for (int am = 0; am < 2; am++)
            #pragma unroll
            for (int an = 0; an < 4; an++)
                MMA16816(acc[am][an], a[am], bh[an]);
        #pragma unroll
        for (int am = 0; am < 2; am++)
            #pragma unroll
            for (int an = 0; an < 4; an++)
                MMA16816(acc[am][an], a[am], bl[an]);
        #pragma unroll
        for (int am = 0; am < 2; am++) {
            uint32_t off = sw_off(arow + am * 16, akc);
            ldsm4(Al + off, a[am][0], a[am][1], a[am][2], a[am][3]);
        }
        #pragma unroll
        for (int am = 0; am < 2; am++)
            #pragma unroll
            for (int an = 0; an < 4; an++)
                MMA16816(acc[am][an], a[am], bh[an]);
    }
}

// Issue one 32-K chunk (A 64 rows + B 128 rows, hi+lo) into stage (ch&1).
// 1536 x 16B loads, 256 threads -> 6 iterations.
__device__ __forceinline__ void issue_chunk(uint32_t sbase, int ch, int tid,
                                            const __nv_bfloat16* Ahi, const __nv_bfloat16* Alo,
                                            int arow0, int aKB,
                                            const __nv_bfloat16* Bhi, const __nv_bfloat16* Blo,
                                            int brow0, int bKB)
{
    uint32_t st = sbase + (uint32_t)(ch & 1) * STAGE;
    #pragma unroll
    for (int i = 0; i < 6; i++) {
        int e = tid + i * 256;
        const __nv_bfloat16* src;
        uint32_t dst;
        if (e < 512) {                          // A hi/lo: 64 rows x 4 chunks
            int mat = e >> 8;
            int rem = e & 255;
            int row = rem >> 2, chunk = rem & 3;
            src = (mat ? Alo : Ahi) + (size_t)(arow0 + row) * aKB + ch * 32 + chunk * 8;
            dst = st + mat * TILE_A + sw_off(row, chunk);
        } else {                                // B hi/lo: 128 rows x 4 chunks
            int f = e - 512;
            int mat = f >> 9;
            int rem = f & 511;
            int row = rem >> 2, chunk = rem & 3;
            src = (mat ? Blo : Bhi) + (size_t)(brow0 + row) * bKB + ch * 32 + chunk * 8;
            dst = st + 2 * TILE_A + mat * TILE_Bb + sw_off(row, chunk);
        }
        CP_ASYNC16(dst, src);
    }
}

// ------------------------ weight prep (once/replay) ------------------------
__global__ void prep_wst(const float* __restrict__ Wl, const float* __restrict__ Wr,
                         __nv_bfloat16* __restrict__ hi, __nv_bfloat16* __restrict__ lo,
                         float* __restrict__ Wf)
{
    int idx = blockIdx.x * blockDim.x + threadIdx.x;
    if (idx >= NGATE * 256) return;
    int n = idx >> 8, k = idx & 255;
    float w = (k < 128) ? Wl[k * NGATE + n] : Wr[(k - 128) * NGATE + n];
    split_bf16(w, &hi[idx], &lo[idx]);
    Wf[k * NGATE + n] = w;
}

__global__ void prep_wleaf(const float* __restrict__ W,
                           __nv_bfloat16* __restrict__ hi, __nv_bfloat16* __restrict__ lo)
{
    int idx = blockIdx.x * blockDim.x + threadIdx.x;
    if (idx >= 256 * KB_LEAF) return;
    int n = idx / KB_LEAF, k = idx % KB_LEAF;
    float w = (k < 300) ? W[k * 256 + n] : 0.0f;
    split_bf16(w, &hi[idx], &lo[idx]);
}

// ------------------------------ leaf GEMM -----------------------------------
// hc = x @ W_leaf + b_leaf. CTA 64x128, A fp32 converted in-kernel.
__global__ void __launch_bounds__(256, 3)
gemm_leaf(const float* __restrict__ A,
          const __nv_bfloat16* __restrict__ Bhi, const __nv_bfloat16* __restrict__ Blo,
          const float* __restrict__ bias,
          __nv_bfloat16* __restrict__ hhi, __nv_bfloat16* __restrict__ hlo,
          float* __restrict__ cOut, int M, int D)
{
    extern __shared__ char smem[];
    const uint32_t sbase = smem_u32(smem);
    char* const tb = smem;

    const int tid = threadIdx.x;
    const int wid = tid >> 5, lane = tid & 31;
    const int wm = wid >> 2, wn = wid & 3;          // 2 x 4 warps
    const int g = lane >> 2, t2 = (lane & 3) << 1;
    const int bm = blockIdx.x * 64;
    const int ny = blockIdx.y;
    const int Kc = KB_LEAF / 32;                    // 10

    float acc[2][4][4];
    #pragma unroll
    for (int i = 0; i < 2; i++)
        #pragma unroll
        for (int j = 0; j < 4; j++)
            #pragma unroll
            for (int q = 0; q < 4; q++) acc[i][j][q] = 0.f;

    float4 aReg[2];

    auto issueB = [&](int ch) {
        uint32_t st = sbase + (uint32_t)(ch & 1) * STAGE + 2 * TILE_A;
        #pragma unroll
        for (int i = 0; i < 4; i++) {
            int e = tid + i * 256;                   // 0..1023
            int mat = e >> 9;                        // 0 hi, 1 lo
            int rem = e & 511;
            int row = rem >> 2, chunk = rem & 3;
            const __nv_bfloat16* src = (mat ? Blo : Bhi)
                + (size_t)(ny * 128 + row) * KB_LEAF + ch * 32 + chunk * 8;
            uint32_t dst = st + mat * TILE_Bb + sw_off(row, chunk);
            CP_ASYNC16(dst, src);
        }
    };
    auto ldA = [&](int ch) {
        #pragma unroll
        for (int i = 0; i < 2; i++) {
            int f = tid + i * 256;                   // 0..511 = 64 rows x 8 quads
            int row = f >> 3, k4 = (f & 7) << 2;
            int k = ch * 32 + k4;
            float4 v = make_float4(0.f, 0.f, 0.f, 0.f);
            if (k < D) v = *(const float4*)(A + (size_t)(bm + row) * D + k);
            aReg[i] = v;
        }
    };
    auto stA = [&](int s) {
        char* st = tb + (s & 1) * STAGE;
        #pragma unroll
        for (int i = 0; i < 2; i++) {
            int f = tid + i * 256;
            int row = f >> 3, k4 = (f & 7) << 2;
            int chunk = k4 >> 3, half = (k4 >> 2) & 1;
            uint32_t off = sw_off(row, chunk) + half * 8;
            float4 v = aReg[i];
            __nv_bfloat16 h0, l0, h1, l1, h2, l2, h3, l3;
            split_bf16(v.x, &h0, &l0); split_bf16(v.y, &h1, &l1);
            split_bf16(v.z, &h2, &l2); split_bf16(v.w, &h3, &l3);
            *(uint2*)(st + off)          = make_uint2(pack_bf(h0, h1), pack_bf(h2, h3));
            *(uint2*)(st + TILE_A + off) = make_uint2(pack_bf(l0, l1), pack_bf(l2, l3));
        }
    };

    issueB(0); CP_COMMIT();
    ldA(0); stA(0);
    issueB(1); CP_COMMIT();
    ldA(1);
    for (int ch = 0; ch < Kc; ch++) {
        if (ch + 1 < Kc) CP_WAIT1(); else CP_WAIT0();
        __syncthreads();                     // stage ch ready; stage ch+1 free of readers
        if (ch + 1 < Kc) stA(ch + 1);        // A(ch+1) -> stage (ch+1)&1
        stage_compute(sbase + (uint32_t)(ch & 1) * STAGE, wm, wn, lane, acc);
        __syncthreads();                     // all done reading stage ch&1
        if (ch + 2 < Kc) { issueB(ch + 2); CP_COMMIT(); ldA(ch + 2); }
    }

    #pragma unroll
    for (int am = 0; am < 2; am++) {
        int r0 = bm + wm * 32 + am * 16 + g;
        #pragma unroll
        for (int an = 0; an < 4; an++) {
            int c  = wn * 32 + an * 8 + t2;
            float b0 = bias[ny * 128 + c], b1 = bias[ny * 128 + c + 1];
            float v00 = acc[am][an][0] + b0, v01 = acc[am][an][1] + b1;
            float v10 = acc[am][an][2] + b0, v11 = acc[am][an][3] + b1;
            if (ny == 0) {
                __nv_bfloat16 h0, l0, h1, l1;
                split_bf16(v00, &h0, &l0); split_bf16(v01, &h1, &l1);
                *(uint32_t*)(hhi + (size_t)r0 * Hc + c) = pack_bf(h0, h1);
                *(uint32_t*)(hlo + (size_t)r0 * Hc + c) = pack_bf(l0, l1);
                split_bf16(v10, &h0, &l0); split_bf16(v11, &h1, &l1);
                *(uint32_t*)(hhi + (size_t)(r0 + 8) * Hc + c) = pack_bf(h0, h1);
                *(uint32_t*)(hlo + (size_t)(r0 + 8) * Hc + c) = pack_bf(l0, l1);
            } else {
                *(float2*)(cOut + (size_t)r0 * Hc + c)       = make_float2(v00, v01);
                *(float2*)(cOut + (size_t)(r0 + 8) * Hc + c) = make_float2(v10, v11);
            }
        }
    }
}

// ------------------------------ level GEMM ----------------------------------
__global__ void __launch_bounds__(256, 3)
gemm_level(const __nv_bfloat16* __restrict__ Ahi, const __nv_bfloat16* __restrict__ Alo,
           const __nv_bfloat16* __restrict__ Bhi, const __nv_bfloat16* __restrict__ Blo,
           const float* __restrict__ bias, float* __restrict__ gates, int M)
{
    extern __shared__ char smem[];
    const uint32_t sbase = smem_u32(smem);

    const int tid = threadIdx.x;
    const int wid = tid >> 5, lane = tid & 31;
    const int wm = wid >> 2, wn = wid & 3;           // 2 x 4 warps
    const int g = lane >> 2, t2 = (lane & 3) << 1;
    const int bm = blockIdx.x * 64;
    const int ny = blockIdx.y;
    const int Kc = 8;                                // K = 256

    float acc[2][4][4];
    #pragma unroll
    for (int i = 0; i < 2; i++)
        #pragma unroll
        for (int j = 0; j < 4; j++)
            #pragma unroll
            for (int q = 0; q < 4; q++) acc[i][j][q] = 0.f;

    issue_chunk(sbase, 0, tid, Ahi, Alo, bm, 256, Bhi, Blo, ny * 128, 256);
    CP_COMMIT();
    issue_chunk(sbase, 1, tid, Ahi, Alo, bm, 256, Bhi, Blo, ny * 128, 256);
    CP_COMMIT();
    for (int ch = 0; ch < Kc; ch++) {
        if (ch + 1 < Kc) CP_WAIT1(); else CP_WAIT0();
        __syncthreads();
        stage_compute(sbase + (uint32_t)(ch & 1) * STAGE, wm, wn, lane, acc);
        __syncthreads();
        if (ch + 2 < Kc) {
            issue_chunk(sbase, ch + 2, tid, Ahi, Alo, bm, 256, Bhi, Blo, ny * 128, 256);
            CP_COMMIT();
        }
    }

    #pragma unroll
    for (int am = 0; am < 2; am++) {
        int r0 = bm + wm * 32 + am * 16 + g;
        #pragma unroll
        for (int an = 0; an < 4; an++) {
            int c  = wn * 32 + an * 8 + t2;
            int gc = ny * 128 + c;
            float b0 = bias[gc], b1 = bias[gc + 1];
            *(float2*)(gates + (size_t)r0 * NGATE + gc)
                = make_float2(acc[am][an][0] + b0, acc[am][an][1] + b1);
            *(float2*)(gates + (size_t)(r0 + 8) * NGATE + gc)
                = make_float2(acc[am][an][2] + b0, acc[am][an][3] + b1);
        }
    }
}

// ------------------------------- LSTM cell ----------------------------------
__global__ void lstm_cell4(const float* __restrict__ gates,
                           const float* __restrict__ c_prev,
                           __nv_bfloat16* __restrict__ hhi, __nv_bfloat16* __restrict__ hlo,
                           float* __restrict__ c_out, int M)
{
    int idx = blockIdx.x * blockDim.x + threadIdx.x;
    if (idx >= M * 32) return;
    int r = idx >> 5, j = (idx & 31) << 2;
    const float* g = gates + (size_t)r * NGATE;
    float4 i4  = *(const float4*)(g + j);
    float4 fl4 = *(const float4*)(g + 128 + j);
    float4 fr4 = *(const float4*)(g + 256 + j);
    float4 o4  = *(const float4*)(g + 384 + j);
    float4 g4  = *(const float4*)(g + 512 + j);
    const float* cp = c_prev + (size_t)r * 256;
    float4 cl4 = *(const float4*)(cp + j);
    float4 cr4 = *(const float4*)(cp + 128 + j);
    float4 c, h;
#define CEL(X) { float ii = sigf(i4.X), fl = sigf(fl4.X), fr = sigf(fr4.X);      \
                 float oo = sigf(o4.X), gg = tanhf(g4.X);                        \
                 float cc = fl * cl4.X + fr * cr4.X + ii * gg;                   \
                 c.X = cc; h.X = oo * tanhf(cc); }
    CEL(x) CEL(y) CEL(z) CEL(w)
#undef CEL
    *(float4*)(c_out + (size_t)r * Hc + j) = c;
    __nv_bfloat16 b0, l0, b1, l1, b2, l2, b3, l3;
    split_bf16(h.x, &b0, &l0); split_bf16(h.y, &b1, &l1);
    split_bf16(h.z, &b2, &l2); split_bf16(h.w, &b3, &l3);
    *(uint2*)(hhi + (size_t)r * Hc + j) = make_uint2(pack_bf(b0, b1), pack_bf(b2, b3));
    *(uint2*)(hlo + (size_t)r * Hc + j) = make_uint2(pack_bf(l0, l1), pack_bf(l2, l3));
}

// --------------------- fused tiny-level kernel (M <= 128) -------------------
#define RSM 2
__global__ void __launch_bounds__(640)
level_small(const __nv_bfloat16* __restrict__ Ahi, const __nv_bfloat16* __restrict__ Alo,
            const float* __restrict__ Wf, const float* __restrict__ bg,
            const float* __restrict__ c_prev,
            __nv_bfloat16* __restrict__ hhi_o, __nv_bfloat16* __restrict__ hlo_o,
            float* __restrict__ c_out, float* __restrict__ hf_out, int M)
{
    __shared__ float hs[RSM][256];
    __shared__ float gs[RSM][NGATE];
    const int tid = threadIdx.x;
    const int r0 = blockIdx.x * RSM;

    for (int idx = tid; idx < RSM * 256; idx += 640) {
        int r = idx >> 8, k = idx & 255;
        int gr = r0 + r;
        float v = 0.f;
        if (gr < M)
            v = __bfloat162float(Ahi[(size_t)gr * 256 + k])
              + __bfloat162float(Alo[(size_t)gr * 256 + k]);
        hs[r][k] = v;
    }
    __syncthreads();

    {
        const int c = tid;
        float a0 = 0.f, a1 = 0.f;
        #pragma unroll 8
        for (int k = 0; k < 256; k++) {
            float w = Wf[k * NGATE + c];
            a0 += hs[0][k] * w; a1 += hs[1][k] * w;
        }
        float b = bg[c];
        gs[0][c] = a0 + b; gs[1][c] = a1 + b;
    }
    __syncthreads();

    if (tid < RSM * 128) {
        int r = tid >> 7, u = tid & 127;
        int gr = r0 + r;
        if (gr < M) {
            float gi = sigf(gs[r][u]);
            float fl = sigf(gs[r][128 + u]);
            float fr = sigf(gs[r][256 + u]);
            float go = sigf(gs[r][384 + u]);
            float gg = tanhf(gs[r][512 + u]);
            float cl = c_prev[(size_t)gr * 256 + u];
            float cr = c_prev[(size_t)gr * 256 + 128 + u];
            float cc = fl * cl + fr * cr + gi * gg;
            float hh = go * tanhf(cc);
            c_out[(size_t)gr * Hc + u] = cc;
            if (hf_out) {
                hf_out[(size_t)gr * Hc + u] = hh;
            } else {
                __nv_bfloat16 hb, lb;
                split_bf16(hh, &hb, &lb);
                hhi_o[(size_t)gr * Hc + u] = hb;
                hlo_o[(size_t)gr * Hc + u] = lb;
            }
        }
    }
}

// --------------------------------- launch -----------------------------------
extern "C" void kernel_launch(void* const* d_in, const int* in_sizes, int n_in,
                              void* d_out, int out_size)
{
    const float* x      = (const float*)d_in[0];
    const float* W_leaf = (const float*)d_in[1];
    const float* b_leaf = (const float*)d_in[2];
    const float* W_l    = (const float*)d_in[3];
    const float* W_r    = (const float*)d_in[4];
    const float* bg     = (const float*)d_in[5];

    const int twoH = in_sizes[2];            // 256
    const int H    = twoH / 2;               // 128
    const int D    = in_sizes[1] / twoH;     // 300
    const int BL   = in_sizes[0] / D;        // 32768
    const int B    = out_size / H;           // 8
    const int L    = BL / B;                 // 4096
    int levels = 0;
    for (int t = L; t > 1; t >>= 1) levels++;

    __nv_bfloat16 *hhiA, *hloA, *hhiB, *hloB, *Wt_hi, *Wt_lo, *Wlf_hi, *Wlf_lo;
    float *cA, *cB, *gates, *Wstf;
    cudaGetSymbolAddress((void**)&hhiA,   g_hhiA);
    cudaGetSymbolAddress((void**)&hloA,   g_hloA);
    cudaGetSymbolAddress((void**)&hhiB,   g_hhiB);
    cudaGetSymbolAddress((void**)&hloB,   g_hloB);
    cudaGetSymbolAddress((void**)&cA,     g_cA);
    cudaGetSymbolAddress((void**)&cB,     g_cB);
    cudaGetSymbolAddress((void**)&gates,  g_gates);
    cudaGetSymbolAddress((void**)&Wstf,   g_Wstf);
    cudaGetSymbolAddress((void**)&Wt_hi,  g_Wt_hi);
    cudaGetSymbolAddress((void**)&Wt_lo,  g_Wt_lo);
    cudaGetSymbolAddress((void**)&Wlf_hi, g_WlfT_hi);
    cudaGetSymbolAddress((void**)&Wlf_lo, g_WlfT_lo);

    cudaFuncSetAttribute(gemm_leaf,  cudaFuncAttributeMaxDynamicSharedMemorySize, SMEM_REQ);
    cudaFuncSetAttribute(gemm_level, cudaFuncAttributeMaxDynamicSharedMemorySize, SMEM_REQ);

    // 1) weight prep
    prep_wst  <<<(NGATE * 256 + 255) / 256, 256>>>(W_l, W_r, Wt_hi, Wt_lo, Wstf);
    prep_wleaf<<<(256 * KB_LEAF + 255) / 256, 256>>>(W_leaf, Wlf_hi, Wlf_lo);

    // 2) leaf GEMM (reads fp32 x directly, converts in-kernel)
    {
        dim3 grid(BL / 64, 2);
        gemm_leaf<<<grid, 256, SMEM_REQ>>>(x, Wlf_hi, Wlf_lo, b_leaf,
                                           hhiA, hloA, cA, BL, D);
    }

    // 3) reduction levels
    __nv_bfloat16 *sh_hi = hhiA, *sh_lo = hloA, *dh_hi = hhiB, *dh_lo = hloB;
    float *sc = cA, *dc = cB;
    int n = L;
    for (int lvl = 0; lvl < levels; lvl++) {
        n >>= 1;
        int M = B * n;
        bool last = (lvl == levels - 1);

        if (M >= 256) {
            dim3 grid(M / 64, 5);
            gemm_level<<<grid, 256, SMEM_REQ>>>(sh_hi, sh_lo, Wt_hi, Wt_lo, bg, gates, M);
            lstm_cell4<<<(M * 32 + 255) / 256, 256>>>(gates, sc, dh_hi, dh_lo, dc, M);
        } else {
            level_small<<<(M + RSM - 1) / RSM, 640>>>(sh_hi, sh_lo, Wstf, bg, sc,
                                                      dh_hi, dh_lo, dc,
                                                      last ? (float*)d_out : nullptr, M);
        }

        __nv_bfloat16* t;
        t = sh_hi; sh_hi = dh_hi; dh_hi = t;
        t = sh_lo; sh_lo = dh_lo; dh_lo = t;
        float* tc = sc; sc = dc; dc = tc;
    }
}

// round 11
// speedup vs baseline: 1.2830x; 1.0820x over previous
#include <cuda_runtime.h>
#include <cuda_bf16.h>
#include <math.h>
#include <stdint.h>

// ---------------------------------------------------------------------------
// TreeLSTM on GB300, mma.sync bf16x3 (tcgen05 feature-gated off on this
// harness's compute_103 target).
// R11: 3-stage (72KB) single-barrier cp.async pipeline at 3 CTAs/SM
// (216KB/SM); fast-math cell activations. CTA tile 64x128, warp tile 32x32,
// regs ~80. D = Ah*Bh + Ah*Bl + Al*Bh, fp32 accumulators.
// ---------------------------------------------------------------------------

#define Hc      128
#define MAXBL   32768
#define NGATE   640
#define KB_LEAF 320

__device__ __align__(128) __nv_bfloat16 g_hhiA[MAXBL * Hc];
__device__ __align__(128) __nv_bfloat16 g_hloA[MAXBL * Hc];
__device__ __align__(128) __nv_bfloat16 g_hhiB[(MAXBL / 2) * Hc];
__device__ __align__(128) __nv_bfloat16 g_hloB[(MAXBL / 2) * Hc];
__device__ float g_cA[MAXBL * Hc];
__device__ float g_cB[(MAXBL / 2) * Hc];
__device__ float g_gates[(MAXBL / 2) * NGATE];
__device__ __align__(128) __nv_bfloat16 g_Wt_hi[NGATE * 256];     // [640,256] K-major
__device__ __align__(128) __nv_bfloat16 g_Wt_lo[NGATE * 256];
__device__ float g_Wstf[256 * NGATE];                             // [256,640] fp32
__device__ __align__(128) __nv_bfloat16 g_WlfT_hi[256 * KB_LEAF]; // [256,320]
__device__ __align__(128) __nv_bfloat16 g_WlfT_lo[256 * KB_LEAF];

// ------------------------------- helpers -----------------------------------
__device__ __forceinline__ uint32_t smem_u32(const void* p) {
    uint32_t a;
    asm("{ .reg .u64 t; cvta.to.shared.u64 t, %1; cvt.u32.u64 %0, t; }"
        : "=r"(a) : "l"(p));
    return a;
}
#define CP_ASYNC16(dst, src) \
    asm volatile("cp.async.cg.shared.global [%0], [%1], 16;" \
                 :: "r"(dst), "l"(src) : "memory")
#define CP_COMMIT() asm volatile("cp.async.commit_group;" ::: "memory")
#define CP_WAIT1()  asm volatile("cp.async.wait_group 1;"  ::: "memory")
#define CP_WAIT0()  asm volatile("cp.async.wait_group 0;"  ::: "memory")

#define MMA16816(c, a, b)                                                      \
    asm volatile("mma.sync.aligned.m16n8k16.row.col.f32.bf16.bf16.f32 "       \
        "{%0,%1,%2,%3},{%4,%5,%6,%7},{%8,%9},{%0,%1,%2,%3};"                  \
        : "+f"((c)[0]), "+f"((c)[1]), "+f"((c)[2]), "+f"((c)[3])              \
        : "r"((a)[0]), "r"((a)[1]), "r"((a)[2]), "r"((a)[3]),                 \
          "r"((b)[0]), "r"((b)[1]))

__device__ __forceinline__ void ldsm4(uint32_t a, uint32_t& r0, uint32_t& r1,
                                      uint32_t& r2, uint32_t& r3) {
    asm volatile("ldmatrix.sync.aligned.m8n8.x4.shared.b16 {%0,%1,%2,%3}, [%4];"
                 : "=r"(r0), "=r"(r1), "=r"(r2), "=r"(r3) : "r"(a));
}

__device__ __forceinline__ void split_bf16(float w, __nv_bfloat16* hi, __nv_bfloat16* lo) {
    __nv_bfloat16 h = __float2bfloat16(w);
    *hi = h;
    *lo = __float2bfloat16(w - __bfloat162float(h));
}
__device__ __forceinline__ uint32_t pack_bf(__nv_bfloat16 a, __nv_bfloat16 b) {
    __nv_bfloat162 t{a, b};
    return *(uint32_t*)&t;
}
// fast-math activations (precision ~1e-6 — well under our error budget)
__device__ __forceinline__ float sigf(float x) {
    return __fdividef(1.0f, 1.0f + __expf(-x));
}
__device__ __forceinline__ float tanf_(float x) {
    float t = __expf(2.0f * x);
    return __fdividef(t - 1.0f, t + 1.0f);
}

// Tiles (K-chunk 32, 64B rows): A 64x32 bf16 = 4KB, B 128x32 bf16 = 8KB.
// Stage: A_hi | A_lo | B_hi | B_lo = 24KB. 3 stages = 72KB -> 3 CTAs/SM (216KB).
#define TILE_A   4096
#define TILE_Bb  8192
#define STAGE    24576
#define SMEM_REQ (3 * STAGE)

// 64B-row swizzle: 16B chunk xor'd with (row>>1)&3 (verified conflict-free R9).
__device__ __forceinline__ uint32_t sw_off(int row, int chunk) {
    return (uint32_t)(row * 64 + ((chunk ^ ((row >> 1) & 3)) << 4));
}

// ---- compute one 32-K chunk: 2 k-steps; 32x32 warp tile (2x4 warp grid) ----
__device__ __forceinline__ void stage_compute(uint32_t st, int wm, int wn, int lane,
                                              float (*acc)[4][4])
{
    const int ts = lane >> 3, rs = lane & 7;
    const uint32_t Ah = st, Al = st + TILE_A;
    const uint32_t Bh = st + 2 * TILE_A, Bl = st + 2 * TILE_A + TILE_Bb;
    const int arow = wm * 32 + ((ts & 1) << 3) + rs;   // + am*16
    const int ach  = ts >> 1;
    const int brow = wn * 32 + ((ts >> 1) << 3) + rs;  // + j*16
    const int bch  = ts & 1;
    #pragma unroll
    for (int kk = 0; kk < 2; kk++) {
        uint32_t a[2][4], bh[4][2], bl[4][2];
        const int akc = kk * 2 + ach;
        const int bkc = kk * 2 + bch;
        #pragma unroll
        for (int j = 0; j < 2; j++) {
            uint32_t off = sw_off(brow + j * 16, bkc);
            ldsm4(Bh + off, bh[2*j][0], bh[2*j][1], bh[2*j+1][0], bh[2*j+1][1]);
            ldsm4(Bl + off, bl[2*j][0], bl[2*j][1], bl[2*j+1][0], bl[2*j+1][1]);
        }
        #pragma unroll
        for (int am = 0; am < 2; am++) {
            uint32_t off = sw_off(arow + am * 16, akc);
            ldsm4(Ah + off, a[am][0], a[am][1], a[am][2], a[am][3]);
        }
        #pragma unroll
        for (int am = 0; am < 2; am++)
            #pragma unroll
            for (int an = 0; an < 4; an++)
                MMA16816(acc[am][an], a[am], bh[an]);
        #pragma unroll
        for (int am = 0; am < 2; am++)
            #pragma unroll
            for (int an = 0; an < 4; an++)
                MMA16816(acc[am][an], a[am], bl[an]);
        #pragma unroll
        for (int am = 0; am < 2; am++) {
            uint32_t off = sw_off(arow + am * 16, akc);
            ldsm4(Al + off, a[am][0], a[am][1], a[am][2], a[am][3]);
        }
        #pragma unroll
        for (int am = 0; am < 2; am++)
            #pragma unroll
            for (int an = 0; an < 4; an++)
                MMA16816(acc[am][an], a[am], bh[an]);
    }
}

// Issue one 32-K chunk (A 64 rows + B 128 rows, hi+lo) into stage (ch%3).
__device__ __forceinline__ void issue_chunk(uint32_t sbase, int ch, int tid,
                                            const __nv_bfloat16* Ahi, const __nv_bfloat16* Alo,
                                            int arow0, int aKB,
                                            const __nv_bfloat16* Bhi, const __nv_bfloat16* Blo,
                                            int brow0, int bKB)
{
    uint32_t st = sbase + (uint32_t)(ch % 3) * STAGE;
    #pragma unroll
    for (int i = 0; i < 6; i++) {
        int e = tid + i * 256;
        const __nv_bfloat16* src;
        uint32_t dst;
        if (e < 512) {                          // A hi/lo: 64 rows x 4 chunks
            int mat = e >> 8;
            int rem = e & 255;
            int row = rem >> 2, chunk = rem & 3;
            src = (mat ? Alo : Ahi) + (size_t)(arow0 + row) * aKB + ch * 32 + chunk * 8;
            dst = st + mat * TILE_A + sw_off(row, chunk);
        } else {                                // B hi/lo: 128 rows x 4 chunks
            int f = e - 512;
            int mat = f >> 9;
            int rem = f & 511;
            int row = rem >> 2, chunk = rem & 3;
            src = (mat ? Blo : Bhi) + (size_t)(brow0 + row) * bKB + ch * 32 + chunk * 8;
            dst = st + 2 * TILE_A + mat * TILE_Bb + sw_off(row, chunk);
        }
        CP_ASYNC16(dst, src);
    }
}

// ------------------------ weight prep (once/replay) ------------------------
__global__ void prep_wst(const float* __restrict__ Wl, const float* __restrict__ Wr,
                         __nv_bfloat16* __restrict__ hi, __nv_bfloat16* __restrict__ lo,
                         float* __restrict__ Wf)
{
    int idx = blockIdx.x * blockDim.x + threadIdx.x;
    if (idx >= NGATE * 256) return;
    int n = idx >> 8, k = idx & 255;
    float w = (k < 128) ? Wl[k * NGATE + n] : Wr[(k - 128) * NGATE + n];
    split_bf16(w, &hi[idx], &lo[idx]);
    Wf[k * NGATE + n] = w;
}

__global__ void prep_wleaf(const float* __restrict__ W,
                           __nv_bfloat16* __restrict__ hi, __nv_bfloat16* __restrict__ lo)
{
    int idx = blockIdx.x * blockDim.x + threadIdx.x;
    if (idx >= 256 * KB_LEAF) return;
    int n = idx / KB_LEAF, k = idx % KB_LEAF;
    float w = (k < 300) ? W[k * 256 + n] : 0.0f;
    split_bf16(w, &hi[idx], &lo[idx]);
}

// ------------------------------ leaf GEMM -----------------------------------
// hc = x @ W_leaf + b_leaf. CTA 64x128, A fp32 converted in-kernel. 3-stage.
__global__ void __launch_bounds__(256, 3)
gemm_leaf(const float* __restrict__ A,
          const __nv_bfloat16* __restrict__ Bhi, const __nv_bfloat16* __restrict__ Blo,
          const float* __restrict__ bias,
          __nv_bfloat16* __restrict__ hhi, __nv_bfloat16* __restrict__ hlo,
          float* __restrict__ cOut, int M, int D)
{
    extern __shared__ char smem[];
    const uint32_t sbase = smem_u32(smem);
    char* const tb = smem;

    const int tid = threadIdx.x;
    const int wid = tid >> 5, lane = tid & 31;
    const int wm = wid >> 2, wn = wid & 3;          // 2 x 4 warps
    const int g = lane >> 2, t2 = (lane & 3) << 1;
    const int bm = blockIdx.x * 64;
    const int ny = blockIdx.y;
    const int Kc = KB_LEAF / 32;                    // 10

    float acc[2][4][4];
    #pragma unroll
    for (int i = 0; i < 2; i++)
        #pragma unroll
        for (int j = 0; j < 4; j++)
            #pragma unroll
            for (int q = 0; q < 4; q++) acc[i][j][q] = 0.f;

    float4 aReg[2];

    auto issueB = [&](int ch) {
        uint32_t st = sbase + (uint32_t)(ch % 3) * STAGE + 2 * TILE_A;
        #pragma unroll
        for (int i = 0; i < 4; i++) {
            int e = tid + i * 256;                   // 0..1023
            int mat = e >> 9;                        // 0 hi, 1 lo
            int rem = e & 511;
            int row = rem >> 2, chunk = rem & 3;
            const __nv_bfloat16* src = (mat ? Blo : Bhi)
                + (size_t)(ny * 128 + row) * KB_LEAF + ch * 32 + chunk * 8;
            uint32_t dst = st + mat * TILE_Bb + sw_off(row, chunk);
            CP_ASYNC16(dst, src);
        }
    };
    auto ldA = [&](int ch) {
        #pragma unroll
        for (int i = 0; i < 2; i++) {
            int f = tid + i * 256;                   // 0..511 = 64 rows x 8 quads
            int row = f >> 3, k4 = (f & 7) << 2;
            int k = ch * 32 + k4;
            float4 v = make_float4(0.f, 0.f, 0.f, 0.f);
            if (k < D) v = *(const float4*)(A + (size_t)(bm + row) * D + k);
            aReg[i] = v;
        }
    };
    auto stA = [&](int s) {
        char* st = tb + (s % 3) * STAGE;
        #pragma unroll
        for (int i = 0; i < 2; i++) {
            int f = tid + i * 256;
            int row = f >> 3, k4 = (f & 7) << 2;
            int chunk = k4 >> 3, half = (k4 >> 2) & 1;
            uint32_t off = sw_off(row, chunk) + half * 8;
            float4 v = aReg[i];
            __nv_bfloat16 h0, l0, h1, l1, h2, l2, h3, l3;
            split_bf16(v.x, &h0, &l0); split_bf16(v.y, &h1, &l1);
            split_bf16(v.z, &h2, &l2); split_bf16(v.w, &h3, &l3);
            *(uint2*)(st + off)          = make_uint2(pack_bf(h0, h1), pack_bf(h2, h3));
            *(uint2*)(st + TILE_A + off) = make_uint2(pack_bf(l0, l1), pack_bf(l2, l3));
        }
    };

    issueB(0); CP_COMMIT();
    ldA(0); stA(0);
    issueB(1); CP_COMMIT();
    ldA(1);
    for (int ch = 0; ch < Kc; ch++) {
        if (ch + 1 < Kc) CP_WAIT1(); else CP_WAIT0();
        __syncthreads();                     // single barrier per chunk
        if (ch + 1 < Kc) stA(ch + 1);        // A(ch+1) -> stage (ch+1)%3
        if (ch + 2 < Kc) { issueB(ch + 2); CP_COMMIT(); ldA(ch + 2); }
        stage_compute(sbase + (uint32_t)(ch % 3) * STAGE, wm, wn, lane, acc);
    }

    #pragma unroll
    for (int am = 0; am < 2; am++) {
        int r0 = bm + wm * 32 + am * 16 + g;
        #pragma unroll
        for (int an = 0; an < 4; an++) {
            int c  = wn * 32 + an * 8 + t2;
            float b0 = bias[ny * 128 + c], b1 = bias[ny * 128 + c + 1];
            float v00 = acc[am][an][0] + b0, v01 = acc[am][an][1] + b1;
            float v10 = acc[am][an][2] + b0, v11 = acc[am][an][3] + b1;
            if (ny == 0) {
                __nv_bfloat16 h0, l0, h1, l1;
                split_bf16(v00, &h0, &l0); split_bf16(v01, &h1, &l1);
                *(uint32_t*)(hhi + (size_t)r0 * Hc + c) = pack_bf(h0, h1);
                *(uint32_t*)(hlo + (size_t)r0 * Hc + c) = pack_bf(l0, l1);
                split_bf16(v10, &h0, &l0); split_bf16(v11, &h1, &l1);
                *(uint32_t*)(hhi + (size_t)(r0 + 8) * Hc + c) = pack_bf(h0, h1);
                *(uint32_t*)(hlo + (size_t)(r0 + 8) * Hc + c) = pack_bf(l0, l1);
            } else {
                *(float2*)(cOut + (size_t)r0 * Hc + c)       = make_float2(v00, v01);
                *(float2*)(cOut + (size_t)(r0 + 8) * Hc + c) = make_float2(v10, v11);
            }
        }
    }
}

// ------------------------------ level GEMM ----------------------------------
__global__ void __launch_bounds__(256, 3)
gemm_level(const __nv_bfloat16* __restrict__ Ahi, const __nv_bfloat16* __restrict__ Alo,
           const __nv_bfloat16* __restrict__ Bhi, const __nv_bfloat16* __restrict__ Blo,
           const float* __restrict__ bias, float* __restrict__ gates, int M)
{
    extern __shared__ char smem[];
    const uint32_t sbase = smem_u32(smem);

    const int tid = threadIdx.x;
    const int wid = tid >> 5, lane = tid & 31;
    const int wm = wid >> 2, wn = wid & 3;           // 2 x 4 warps
    const int g = lane >> 2, t2 = (lane & 3) << 1;
    const int bm = blockIdx.x * 64;
    const int ny = blockIdx.y;
    const int Kc = 8;                                // K = 256

    float acc[2][4][4];
    #pragma unroll
    for (int i = 0; i < 2; i++)
        #pragma unroll
        for (int j = 0; j < 4; j++)
            #pragma unroll
            for (int q = 0; q < 4; q++) acc[i][j][q] = 0.f;

    issue_chunk(sbase, 0, tid, Ahi, Alo, bm, 256, Bhi, Blo, ny * 128, 256);
    CP_COMMIT();
    issue_chunk(sbase, 1, tid, Ahi, Alo, bm, 256, Bhi, Blo, ny * 128, 256);
    CP_COMMIT();
    for (int ch = 0; ch < Kc; ch++) {
        if (ch + 1 < Kc) CP_WAIT1(); else CP_WAIT0();
        __syncthreads();                     // single barrier per chunk
        if (ch + 2 < Kc) {
            issue_chunk(sbase, ch + 2, tid, Ahi, Alo, bm, 256, Bhi, Blo, ny * 128, 256);
            CP_COMMIT();
        }
        stage_compute(sbase + (uint32_t)(ch % 3) * STAGE, wm, wn, lane, acc);
    }

    #pragma unroll
    for (int am = 0; am < 2; am++) {
        int r0 = bm + wm * 32 + am * 16 + g;
        #pragma unroll
        for (int an = 0; an < 4; an++) {
            int c  = wn * 32 + an * 8 + t2;
            int gc = ny * 128 + c;
            float b0 = bias[gc], b1 = bias[gc + 1];
            *(float2*)(gates + (size_t)r0 * NGATE + gc)
                = make_float2(acc[am][an][0] + b0, acc[am][an][1] + b1);
            *(float2*)(gates + (size_t)(r0 + 8) * NGATE + gc)
                = make_float2(acc[am][an][2] + b0, acc[am][an][3] + b1);
        }
    }
}

// ------------------------------- LSTM cell ----------------------------------
__global__ void lstm_cell4(const float* __restrict__ gates,
                           const float* __restrict__ c_prev,
                           __nv_bfloat16* __restrict__ hhi, __nv_bfloat16* __restrict__ hlo,
                           float* __restrict__ c_out, int M)
{
    int idx = blockIdx.x * blockDim.x + threadIdx.x;
    if (idx >= M * 32) return;
    int r = idx >> 5, j = (idx & 31) << 2;
    const float* g = gates + (size_t)r * NGATE;
    float4 i4  = *(const float4*)(g + j);
    float4 fl4 = *(const float4*)(g + 128 + j);
    float4 fr4 = *(const float4*)(g + 256 + j);
    float4 o4  = *(const float4*)(g + 384 + j);
    float4 g4  = *(const float4*)(g + 512 + j);
    const float* cp = c_prev + (size_t)r * 256;
    float4 cl4 = *(const float4*)(cp + j);
    float4 cr4 = *(const float4*)(cp + 128 + j);
    float4 c, h;
#define CEL(X) { float ii = sigf(i4.X), fl = sigf(fl4.X), fr = sigf(fr4.X);      \
                 float oo = sigf(o4.X), gg = tanf_(g4.X);                        \
                 float cc = fl * cl4.X + fr * cr4.X + ii * gg;                   \
                 c.X = cc; h.X = oo * tanf_(cc); }
    CEL(x) CEL(y) CEL(z) CEL(w)
#undef CEL
    *(float4*)(c_out + (size_t)r * Hc + j) = c;
    __nv_bfloat16 b0, l0, b1, l1, b2, l2, b3, l3;
    split_bf16(h.x, &b0, &l0); split_bf16(h.y, &b1, &l1);
    split_bf16(h.z, &b2, &l2); split_bf16(h.w, &b3, &l3);
    *(uint2*)(hhi + (size_t)r * Hc + j) = make_uint2(pack_bf(b0, b1), pack_bf(b2, b3));
    *(uint2*)(hlo + (size_t)r * Hc + j) = make_uint2(pack_bf(l0, l1), pack_bf(l2, l3));
}

// --------------------- fused tiny-level kernel (M <= 128) -------------------
#define RSM 2
__global__ void __launch_bounds__(640)
level_small(const __nv_bfloat16* __restrict__ Ahi, const __nv_bfloat16* __restrict__ Alo,
            const float* __restrict__ Wf, const float* __restrict__ bg,
            const float* __restrict__ c_prev,
            __nv_bfloat16* __restrict__ hhi_o, __nv_bfloat16* __restrict__ hlo_o,
            float* __restrict__ c_out, float* __restrict__ hf_out, int M)
{
    __shared__ float hs[RSM][256];
    __shared__ float gs[RSM][NGATE];
    const int tid = threadIdx.x;
    const int r0 = blockIdx.x * RSM;

    for (int idx = tid; idx < RSM * 256; idx += 640) {
        int r = idx >> 8, k = idx & 255;
        int gr = r0 + r;
        float v = 0.f;
        if (gr < M)
            v = __bfloat162float(Ahi[(size_t)gr * 256 + k])
              + __bfloat162float(Alo[(size_t)gr * 256 + k]);
        hs[r][k] = v;
    }
    __syncthreads();

    {
        const int c = tid;
        float a0 = 0.f, a1 = 0.f;
        #pragma unroll 8
        for (int k = 0; k < 256; k++) {
            float w = Wf[k * NGATE + c];
            a0 += hs[0][k] * w; a1 += hs[1][k] * w;
        }
        float b = bg[c];
        gs[0][c] = a0 + b; gs[1][c] = a1 + b;
    }
    __syncthreads();

    if (tid < RSM * 128) {
        int r = tid >> 7, u = tid & 127;
        int gr = r0 + r;
        if (gr < M) {
            float gi = sigf(gs[r][u]);
            float fl = sigf(gs[r][128 + u]);
            float fr = sigf(gs[r][256 + u]);
            float go = sigf(gs[r][384 + u]);
            float gg = tanf_(gs[r][512 + u]);
            float cl = c_prev[(size_t)gr * 256 + u];
            float cr = c_prev[(size_t)gr * 256 + 128 + u];
            float cc = fl * cl + fr * cr + gi * gg;
            float hh = go * tanf_(cc);
            c_out[(size_t)gr * Hc + u] = cc;
            if (hf_out) {
                hf_out[(size_t)gr * Hc + u] = hh;
            } else {
                __nv_bfloat16 hb, lb;
                split_bf16(hh, &hb, &lb);
                hhi_o[(size_t)gr * Hc + u] = hb;
                hlo_o[(size_t)gr * Hc + u] = lb;
            }
        }
    }
}

// --------------------------------- launch -----------------------------------
extern "C" void kernel_launch(void* const* d_in, const int* in_sizes, int n_in,
                              void* d_out, int out_size)
{
    const float* x      = (const float*)d_in[0];
    const float* W_leaf = (const float*)d_in[1];
    const float* b_leaf = (const float*)d_in[2];
    const float* W_l    = (const float*)d_in[3];
    const float* W_r    = (const float*)d_in[4];
    const float* bg     = (const float*)d_in[5];

    const int twoH = in_sizes[2];            // 256
    const int H    = twoH / 2;               // 128
    const int D    = in_sizes[1] / twoH;     // 300
    const int BL   = in_sizes[0] / D;        // 32768
    const int B    = out_size / H;           // 8
    const int L    = BL / B;                 // 4096
    int levels = 0;
    for (int t = L; t > 1; t >>= 1) levels++;

    __nv_bfloat16 *hhiA, *hloA, *hhiB, *hloB, *Wt_hi, *Wt_lo, *Wlf_hi, *Wlf_lo;
    float *cA, *cB, *gates, *Wstf;
    cudaGetSymbolAddress((void**)&hhiA,   g_hhiA);
    cudaGetSymbolAddress((void**)&hloA,   g_hloA);
    cudaGetSymbolAddress((void**)&hhiB,   g_hhiB);
    cudaGetSymbolAddress((void**)&hloB,   g_hloB);
    cudaGetSymbolAddress((void**)&cA,     g_cA);
    cudaGetSymbolAddress((void**)&cB,     g_cB);
    cudaGetSymbolAddress((void**)&gates,  g_gates);
    cudaGetSymbolAddress((void**)&Wstf,   g_Wstf);
    cudaGetSymbolAddress((void**)&Wt_hi,  g_Wt_hi);
    cudaGetSymbolAddress((void**)&Wt_lo,  g_Wt_lo);
    cudaGetSymbolAddress((void**)&Wlf_hi, g_WlfT_hi);
    cudaGetSymbolAddress((void**)&Wlf_lo, g_WlfT_lo);

    cudaFuncSetAttribute(gemm_leaf,  cudaFuncAttributeMaxDynamicSharedMemorySize, SMEM_REQ);
    cudaFuncSetAttribute(gemm_level, cudaFuncAttributeMaxDynamicSharedMemorySize, SMEM_REQ);

    // 1) weight prep
    prep_wst  <<<(NGATE * 256 + 255) / 256, 256>>>(W_l, W_r, Wt_hi, Wt_lo, Wstf);
    prep_wleaf<<<(256 * KB_LEAF + 255) / 256, 256>>>(W_leaf, Wlf_hi, Wlf_lo);

    // 2) leaf GEMM (reads fp32 x directly, converts in-kernel)
    {
        dim3 grid(BL / 64, 2);
        gemm_leaf<<<grid, 256, SMEM_REQ>>>(x, Wlf_hi, Wlf_lo, b_leaf,
                                           hhiA, hloA, cA, BL, D);
    }

    // 3) reduction levels
    __nv_bfloat16 *sh_hi = hhiA, *sh_lo = hloA, *dh_hi = hhiB, *dh_lo = hloB;
    float *sc = cA, *dc = cB;
    int n = L;
    for (int lvl = 0; lvl < levels; lvl++) {
        n >>= 1;
        int M = B * n;
        bool last = (lvl == levels - 1);

        if (M >= 256) {
            dim3 grid(M / 64, 5);
            gemm_level<<<grid, 256, SMEM_REQ>>>(sh_hi, sh_lo, Wt_hi, Wt_lo, bg, gates, M);
            lstm_cell4<<<(M * 32 + 255) / 256, 256>>>(gates, sc, dh_hi, dh_lo, dc, M);
        } else {
            level_small<<<(M + RSM - 1) / RSM, 640>>>(sh_hi, sh_lo, Wstf, bg, sc,
                                                      dh_hi, dh_lo, dc,
                                                      last ? (float*)d_out : nullptr, M);
        }

        __nv_bfloat16* t;
        t = sh_hi; sh_hi = dh_hi; dh_hi = t;
        t = sh_lo; sh_lo = dh_lo; dh_lo = t;
        float* tc = sc; sc = dc; dc = tc;
    }
}